// round 9
// baseline (speedup 1.0000x reference)
#include <cuda_runtime.h>
#include <cuda_bf16.h>
#include <cuda_fp16.h>
#include <cstdint>

#define B_    32
#define N_    8
#define CIN   3
#define HWD   224
#define PATCH 32
#define S_    49
#define C_    384
#define HM_   512
#define CO_   256
#define NP    12544
#define KCONV 3072
#define NE    2048
#define NAG   1024
#define NIMG  (B_*N_*CIN*HWD*HWD)

// ---- scratch (static device globals; no allocation) ----
__device__ __align__(16) __half g_img_h[NIMG];
__device__ __align__(16) __half g_Wph[C_ * KCONV];
__device__ __align__(16) __half g_W1t_h[NAG * C_];
__device__ __align__(16) __half g_feats_h[NP * C_];
__device__ __align__(16) __half g_feats_l[NP * C_];
__device__ float g_a[NP * HM_];
__device__ float g_g[NP * HM_];
__device__ float g_mask[NE];
__device__ float g_W2h[HM_ * 7];
__device__ float g_bias7[7];

// ---- helpers ----
__device__ __forceinline__ uint32_t smem_to_u32(const void* p) {
    uint32_t a;
    asm("{ .reg .u64 t; cvta.to.shared.u64 t, %1; cvt.u32.u64 %0, t; }" : "=r"(a) : "l"(p));
    return a;
}
__device__ __forceinline__ void cp16(uint32_t dst, const void* src) {
    asm volatile("cp.async.cg.shared.global [%0], [%1], 16;" :: "r"(dst), "l"(src));
}
#define CP_COMMIT() asm volatile("cp.async.commit_group;" ::: "memory")
#define CP_WAIT1()  asm volatile("cp.async.wait_group 1;" ::: "memory")
#define CP_WAIT0()  asm volatile("cp.async.wait_group 0;" ::: "memory")

__device__ __forceinline__ void ldm4(uint32_t* r, uint32_t addr) {
    asm volatile("ldmatrix.sync.aligned.m8n8.x4.shared.b16 {%0,%1,%2,%3}, [%4];"
                 : "=r"(r[0]), "=r"(r[1]), "=r"(r[2]), "=r"(r[3]) : "r"(addr));
}
__device__ __forceinline__ void mma_f16(float* c, const uint32_t* a,
                                        uint32_t b0, uint32_t b1) {
    asm volatile(
        "mma.sync.aligned.m16n8k16.row.col.f32.f16.f16.f32 "
        "{%0,%1,%2,%3}, {%4,%5,%6,%7}, {%8,%9}, {%0,%1,%2,%3};"
        : "+f"(c[0]), "+f"(c[1]), "+f"(c[2]), "+f"(c[3])
        : "r"(a[0]), "r"(a[1]), "r"(a[2]), "r"(a[3]), "r"(b0), "r"(b1));
}
__device__ __forceinline__ void hsplit2(float x, float y, uint32_t& hp, uint32_t& lp) {
    __half hx = __float2half_rn(x), hy = __float2half_rn(y);
    __half lx = __float2half_rn(x - __half2float(hx));
    __half ly = __float2half_rn(y - __half2float(hy));
    __half2 h(hx, hy), l(lx, ly);
    hp = *reinterpret_cast<uint32_t*>(&h);
    lp = *reinterpret_cast<uint32_t*>(&l);
}

// smem rows: 64 fp16 (128B) padded to 144B (conflict-free: stride 16 mod 128)
#define ROWB    144
#define TILE_B  (128 * ROWB)            /* 18432 */
// patch (1-pass fp16): A + B
#define P_STAGE  (2 * TILE_B)           /* 36864 */
#define P_SMEM   (2 * P_STAGE)          /* 73728 */
#define POFF_A   0
#define POFF_B   TILE_B
// ag (2-pass fp16): Ah + Al + Bh
#define AG_STAGE (3 * TILE_B)           /* 55296 */
#define AG_SMEM  (2 * AG_STAGE)         /* 110592 */
#define OFF_AH   0
#define OFF_AL   TILE_B
#define OFF_BH   (2 * TILE_B)

// ============================================================
// Prep kernels
// ============================================================
__global__ void img_prep(const float* __restrict__ img)
{
    long i8 = ((long)blockIdx.x * blockDim.x + threadIdx.x) * 8;
    if (i8 >= NIMG) return;
    float4 v0 = *(const float4*)&img[i8];
    float4 v1 = *(const float4*)&img[i8 + 4];
    __half2 a = __floats2half2_rn(v0.x, v0.y);
    __half2 b = __floats2half2_rn(v0.z, v0.w);
    __half2 c = __floats2half2_rn(v1.x, v1.y);
    __half2 d = __floats2half2_rn(v1.z, v1.w);
    *(uint4*)&g_img_h[i8] = make_uint4(*reinterpret_cast<uint32_t*>(&a),
                                       *reinterpret_cast<uint32_t*>(&b),
                                       *reinterpret_cast<uint32_t*>(&c),
                                       *reinterpret_cast<uint32_t*>(&d));
}

__global__ void wp_prep(const float* __restrict__ Wp)
{
    int i4 = blockIdx.x * blockDim.x + threadIdx.x;
    if (i4 >= C_ * KCONV / 4) return;
    float4 v = *(const float4*)&Wp[i4 * 4];
    __half2 a = __floats2half2_rn(v.x, v.y);
    __half2 b = __floats2half2_rn(v.z, v.w);
    *(uint2*)&g_Wph[i4 * 4] = make_uint2(*reinterpret_cast<uint32_t*>(&a),
                                         *reinterpret_cast<uint32_t*>(&b));
}

__global__ void w1_prep(const float* __restrict__ W1a, const float* __restrict__ W1b)
{
    int idx = blockIdx.x * blockDim.x + threadIdx.x;
    if (idx >= NAG * C_) return;
    int n = idx / C_, k = idx - n * C_;
    float v = (n < HM_) ? W1a[k * HM_ + n] : W1b[k * HM_ + (n - HM_)];
    g_W1t_h[idx] = __float2half_rn(v);
}

// ============================================================
// Patch GEMM: feats = im2row(img_h) x Wp^T, fp16 1-pass, K-chunk 64
// grid (98, 3), 256 thr, 72KB smem, occ 2, 48 chunks
// ============================================================
__global__ void __launch_bounds__(256, 2)
patch_mma_kernel(const float* __restrict__ bp)
{
    extern __shared__ __align__(128) char smem[];
    const uint32_t sb = smem_to_u32(smem);
    const int tid = threadIdx.x, lane = tid & 31, w = tid >> 5;
    const int wm = w >> 2, wn = w & 3;
    const int bm = blockIdx.x * 128, bn = blockIdx.y * 128;

    // loaders: row = tid>>1, seg = tid&1 (32 fp16 = 64B each)
    const int lrow = tid >> 1, lseg = tid & 1;
    int abase;
    {
        int p  = bm + lrow;
        int n  = p / 49;
        int s  = p - n * 49;
        int py = s / 7, px = s - py * 7;
        abase = (n * CIN * HWD + py * PATCH) * HWD + px * PATCH;
    }
    const long brow = (long)(bn + lrow) * KCONV + lseg * 32;

    float acc[4][4][4];
#pragma unroll
    for (int mi = 0; mi < 4; mi++)
#pragma unroll
        for (int ni = 0; ni < 4; ni++)
#pragma unroll
            for (int t = 0; t < 4; t++) acc[mi][ni][t] = 0.f;

    auto cpAB = [&](int c, int st) {
        int k0 = c * 64;
        int ci = k0 >> 10, rem = k0 & 1023, y = rem >> 5;
        // A: 64 k-values = image rows y, y+1 within channel ci (never crosses ci)
        const __half* asrc = g_img_h + abase + ci * (HWD * HWD) + (y + lseg) * HWD;
        uint32_t ad = sb + st * P_STAGE + POFF_A + lrow * ROWB + lseg * 64;
        cp16(ad, asrc); cp16(ad + 16, asrc + 8);
        cp16(ad + 32, asrc + 16); cp16(ad + 48, asrc + 24);
        const __half* bsrc = g_Wph + brow + k0;
        uint32_t bd = sb + st * P_STAGE + POFF_B + lrow * ROWB + lseg * 64;
        cp16(bd, bsrc); cp16(bd + 16, bsrc + 8);
        cp16(bd + 32, bsrc + 16); cp16(bd + 48, bsrc + 24);
    };

    cpAB(0, 0); CP_COMMIT();

    const int NC = KCONV / 64;   // 48
#pragma unroll 1
    for (int c = 0; c < NC; c++) {
        int s = c & 1;
        bool more = (c + 1 < NC);
        if (more) { cpAB(c + 1, s ^ 1); CP_COMMIT(); CP_WAIT1(); }
        else      { CP_WAIT0(); }
        __syncthreads();
        {
            const uint32_t sbase = sb + s * P_STAGE;
#pragma unroll
            for (int step = 0; step < 4; step++) {
                const uint32_t co = (uint32_t)(step * 32 + (lane >> 4) * 16);
                uint32_t bf[2][4];
#pragma unroll
                for (int nj = 0; nj < 2; nj++) {
                    uint32_t ro = (uint32_t)((wn * 32 + nj * 16 + (lane & 15)) * ROWB) + co;
                    ldm4(bf[nj], sbase + POFF_B + ro);
                }
#pragma unroll
                for (int mi = 0; mi < 4; mi++) {
                    uint32_t af[4];
                    uint32_t ro = (uint32_t)((wm * 64 + mi * 16 + (lane & 15)) * ROWB) + co;
                    ldm4(af, sbase + POFF_A + ro);
#pragma unroll
                    for (int ni = 0; ni < 4; ni++) {
                        int nj = ni >> 1, o = ni & 1;
                        mma_f16(acc[mi][ni], af, bf[nj][o], bf[nj][o + 2]);
                    }
                }
            }
        }
        __syncthreads();
    }

    const int r  = lane >> 2;
    const int cc = (lane & 3) * 2;
#pragma unroll
    for (int mi = 0; mi < 4; mi++) {
#pragma unroll
        for (int ni = 0; ni < 4; ni++) {
            int m0  = bm + wm * 64 + mi * 16 + r;
            int col = bn + wn * 32 + ni * 8 + cc;
            float b0 = bp[col], b1 = bp[col + 1];
            uint32_t hp, lp;
            hsplit2(acc[mi][ni][0] + b0, acc[mi][ni][1] + b1, hp, lp);
            *(uint32_t*)&g_feats_h[(long)m0 * C_ + col] = hp;
            *(uint32_t*)&g_feats_l[(long)m0 * C_ + col] = lp;
            hsplit2(acc[mi][ni][2] + b0, acc[mi][ni][3] + b1, hp, lp);
            *(uint32_t*)&g_feats_h[(long)(m0 + 8) * C_ + col] = hp;
            *(uint32_t*)&g_feats_l[(long)(m0 + 8) * C_ + col] = lp;
        }
    }
}

// ============================================================
// a|g GEMM: [12544 x 1024] = feats x W1t^T, fp16 2-pass, K-chunk 64
// grid (98, 8), 108KB smem, occ 2, 6 chunks
// ============================================================
__global__ void __launch_bounds__(256, 2)
ag_mma_kernel()
{
    extern __shared__ __align__(128) char smem[];
    const uint32_t sb = smem_to_u32(smem);
    const int tid = threadIdx.x, lane = tid & 31, w = tid >> 5;
    const int wm = w >> 2, wn = w & 3;
    const int bm = blockIdx.x * 128, bn = blockIdx.y * 128;

    const int lrow = tid >> 1, lseg = tid & 1;
    const long arow = (long)(bm + lrow) * C_ + lseg * 32;
    const long brow = (long)(bn + lrow) * C_ + lseg * 32;

    float acc[4][4][4];
#pragma unroll
    for (int mi = 0; mi < 4; mi++)
#pragma unroll
        for (int ni = 0; ni < 4; ni++)
#pragma unroll
            for (int t = 0; t < 4; t++) acc[mi][ni][t] = 0.f;

    auto cpAB = [&](int c, int st) {
        int k0 = c * 64;
        uint32_t base = sb + st * AG_STAGE + lrow * ROWB + lseg * 64;
        const __half* ah = g_feats_h + arow + k0;
        const __half* al = g_feats_l + arow + k0;
        const __half* bh = g_W1t_h + brow + k0;
        cp16(base + OFF_AH, ah);      cp16(base + OFF_AH + 16, ah + 8);
        cp16(base + OFF_AH + 32, ah + 16); cp16(base + OFF_AH + 48, ah + 24);
        cp16(base + OFF_AL, al);      cp16(base + OFF_AL + 16, al + 8);
        cp16(base + OFF_AL + 32, al + 16); cp16(base + OFF_AL + 48, al + 24);
        cp16(base + OFF_BH, bh);      cp16(base + OFF_BH + 16, bh + 8);
        cp16(base + OFF_BH + 32, bh + 16); cp16(base + OFF_BH + 48, bh + 24);
    };

    cpAB(0, 0); CP_COMMIT();

    const int NC = C_ / 64;   // 6
#pragma unroll 1
    for (int c = 0; c < NC; c++) {
        int s = c & 1;
        bool more = (c + 1 < NC);
        if (more) { cpAB(c + 1, s ^ 1); CP_COMMIT(); CP_WAIT1(); }
        else      { CP_WAIT0(); }
        __syncthreads();
        {
            const uint32_t sbase = sb + s * AG_STAGE;
#pragma unroll
            for (int step = 0; step < 4; step++) {
                const uint32_t co = (uint32_t)(step * 32 + (lane >> 4) * 16);
                uint32_t bf[2][4];
#pragma unroll
                for (int nj = 0; nj < 2; nj++) {
                    uint32_t ro = (uint32_t)((wn * 32 + nj * 16 + (lane & 15)) * ROWB) + co;
                    ldm4(bf[nj], sbase + OFF_BH + ro);
                }
#pragma unroll
                for (int mi = 0; mi < 4; mi++) {
                    uint32_t afh[4], afl[4];
                    uint32_t ro = (uint32_t)((wm * 64 + mi * 16 + (lane & 15)) * ROWB) + co;
                    ldm4(afh, sbase + OFF_AH + ro);
                    ldm4(afl, sbase + OFF_AL + ro);
#pragma unroll
                    for (int ni = 0; ni < 4; ni++) {
                        int nj = ni >> 1, o = ni & 1;
                        mma_f16(acc[mi][ni], afh, bf[nj][o], bf[nj][o + 2]);
                        mma_f16(acc[mi][ni], afl, bf[nj][o], bf[nj][o + 2]);
                    }
                }
            }
        }
        __syncthreads();
    }

    float* dst = (bn < HM_) ? g_a : g_g;
    const int nb = (bn < HM_) ? bn : bn - HM_;
    const int r  = lane >> 2;
    const int cc = (lane & 3) * 2;
#pragma unroll
    for (int mi = 0; mi < 4; mi++) {
#pragma unroll
        for (int ni = 0; ni < 4; ni++) {
            int m0  = bm + wm * 64 + mi * 16 + r;
            int col = nb + wn * 32 + ni * 8 + cc;
            *(float2*)&dst[(long)m0 * HM_ + col] =
                make_float2(acc[mi][ni][0], acc[mi][ni][1]);
            *(float2*)&dst[(long)(m0 + 8) * HM_ + col] =
                make_float2(acc[mi][ni][2], acc[mi][ni][3]);
        }
    }
}

// ============================================================
// mask kernel
// ============================================================
__global__ void mask_kernel(const float* __restrict__ pos, float* __restrict__ out)
{
    int e = blockIdx.x * blockDim.x + threadIdx.x;
    if (e >= NE) return;
    int b = e >> 6, i = (e >> 3) & 7, j = e & 7;
    float xi = pos[(b * N_ + i) * 3 + 0], yi = pos[(b * N_ + i) * 3 + 1];
    float xj = pos[(b * N_ + j) * 3 + 0], yj = pos[(b * N_ + j) * 3 + 1];
    float dx = xi - xj, dy = yi - yj;
    float d2 = __fadd_rn(__fmul_rn(dx, dx), __fmul_rn(dy, dy));
    float m = (d2 < 0.25f && i != j) ? 1.0f : 0.0f;
    g_mask[e] = m;
    out[NE * 7 + e] = m;
}

// ============================================================
// w2h kernel: warp-per-h-row
// ============================================================
__device__ __forceinline__ float head_w(int o, int k,
                                        const float* Wph, const float* Wpv,
                                        const float* Wr, const float* Wrv)
{
    if (k < 2) return Wph[o * 2 + k];
    if (k < 4) return Wpv[o * 2 + (k - 2)];
    if (k < 6) return Wr[o * 2 + (k - 4)];
    return Wrv[o];
}

__global__ void __launch_bounds__(256)
w2h_kernel(const float* __restrict__ W2, const float* __restrict__ b2,
           const float* __restrict__ Wph, const float* __restrict__ bph,
           const float* __restrict__ Wpv, const float* __restrict__ bpv,
           const float* __restrict__ Wr,  const float* __restrict__ br,
           const float* __restrict__ Wrv, const float* __restrict__ brv)
{
    __shared__ float sW[CO_][7];
    const int tid = threadIdx.x, lane = tid & 31, wid = tid >> 5;

    if (tid < CO_) {
#pragma unroll
        for (int k = 0; k < 7; k++)
            sW[tid][k] = head_w(tid, k, Wph, Wpv, Wr, Wrv);
    }
    __syncthreads();

    const int h = blockIdx.x * 8 + wid;
    float acc[7] = {0, 0, 0, 0, 0, 0, 0};
#pragma unroll
    for (int t = 0; t < 8; t++) {
        int o = lane + 32 * t;
        float w2 = W2[h * CO_ + o];
#pragma unroll
        for (int k = 0; k < 7; k++)
            acc[k] = fmaf(w2, sW[o][k], acc[k]);
    }
#pragma unroll
    for (int k = 0; k < 7; k++) {
#pragma unroll
        for (int off = 16; off; off >>= 1)
            acc[k] += __shfl_down_sync(0xffffffffu, acc[k], off);
    }
    if (lane == 0) {
#pragma unroll
        for (int k = 0; k < 7; k++)
            g_W2h[h * 7 + k] = acc[k] * (1.0f / 49.0f);
    }

    if (blockIdx.x == 0 && tid < 7) {
        float sum = 0.f;
        for (int o = 0; o < CO_; o++)
            sum = fmaf(b2[o], sW[o][tid], sum);
        float bb = (tid < 2) ? bph[tid] : (tid < 4) ? bpv[tid - 2]
                 : (tid < 6) ? br[tid - 4] : brv[0];
        g_bias7[tid] = sum + bb;
    }
}

// ============================================================
// edge kernel: one block per (b, i); 512 threads (h = tid); 8 j-accums
// ============================================================
__global__ void __launch_bounds__(512, 2)
edge_b_kernel(const float* __restrict__ b1, float* __restrict__ out)
{
    __shared__ float red[16][28];
    __shared__ float sbias[7];

    const int blk = blockIdx.x;
    const int b   = blk >> 3;
    const int i   = blk & 7;
    const int tid = threadIdx.x, lane = tid & 31, wid = tid >> 5;

    if (tid < 7) sbias[tid] = g_bias7[tid];

    const float base = b1[tid];
    const float* __restrict__ ap = g_a + ((long)(b * 8 + i) * 49) * HM_ + tid;
    const float* __restrict__ gp = g_g + ((long)(b * 8) * 49) * HM_ + tid;

    float acc[8];
#pragma unroll
    for (int j = 0; j < 8; j++) acc[j] = 0.f;

#pragma unroll 1
    for (int s = 0; s < 49; s++) {
        const int so = s * HM_;
        float av = ap[so] + base;
        float gv[8];
#pragma unroll
        for (int j = 0; j < 8; j++)
            gv[j] = gp[j * (49 * HM_) + so];
#pragma unroll
        for (int j = 0; j < 8; j++)
            acc[j] += fmaxf(av + gv[j], 0.f);
    }

    float wv[7];
#pragma unroll
    for (int k = 0; k < 7; k++) wv[k] = g_W2h[tid * 7 + k];

    __syncthreads();

#pragma unroll 1
    for (int p0 = 0; p0 < 8; p0 += 4) {
        float pr[28];
#pragma unroll
        for (int q = 0; q < 4; q++)
#pragma unroll
            for (int k = 0; k < 7; k++)
                pr[q * 7 + k] = acc[p0 + q] * wv[k];
#pragma unroll
        for (int t = 0; t < 28; t++) {
#pragma unroll
            for (int off = 16; off; off >>= 1)
                pr[t] += __shfl_down_sync(0xffffffffu, pr[t], off);
        }
        if (lane == 0) {
#pragma unroll
            for (int t = 0; t < 28; t++) red[wid][t] = pr[t];
        }
        __syncthreads();
        if (tid < 28) {
            float v = 0.f;
#pragma unroll
            for (int ww = 0; ww < 16; ww++) v += red[ww][tid];
            int q = tid / 7, k = tid - 7 * q;
            int j = p0 + q;
            int e = b * 64 + i * 8 + j;
            float mf = g_mask[e];
            out[e * 7 + k] = (mf != 0.f) ? (v + sbias[k]) : 0.f;
        }
        __syncthreads();
    }
}

// ============================================================
// zero-fill node_preds section
// ============================================================
__global__ void zero_kernel(float* __restrict__ out, int n0, int n1)
{
    int idx = n0 + blockIdx.x * blockDim.x + threadIdx.x;
    if (idx < n1) out[idx] = 0.0f;
}

// ============================================================
extern "C" void kernel_launch(void* const* d_in, const int* in_sizes, int n_in,
                              void* d_out, int out_size)
{
    const float* img    = (const float*)d_in[0];
    const float* pos    = (const float*)d_in[1];
    /* d_in[2] = rot, unused */
    const float* Wpatch = (const float*)d_in[3];
    const float* bpatch = (const float*)d_in[4];
    const float* W1a    = (const float*)d_in[5];
    const float* W1b    = (const float*)d_in[6];
    const float* b1     = (const float*)d_in[7];
    const float* W2     = (const float*)d_in[8];
    const float* b2     = (const float*)d_in[9];
    const float* Wp     = (const float*)d_in[10];
    const float* bp     = (const float*)d_in[11];
    const float* Wpv    = (const float*)d_in[12];
    const float* bpv    = (const float*)d_in[13];
    const float* Wr     = (const float*)d_in[14];
    const float* br     = (const float*)d_in[15];
    const float* Wrv    = (const float*)d_in[16];
    const float* brv    = (const float*)d_in[17];
    float* out = (float*)d_out;

    cudaFuncSetAttribute(patch_mma_kernel,
                         cudaFuncAttributeMaxDynamicSharedMemorySize, P_SMEM);
    cudaFuncSetAttribute(ag_mma_kernel,
                         cudaFuncAttributeMaxDynamicSharedMemorySize, AG_SMEM);

    // independent prep
    img_prep<<<NIMG / (256 * 8), 256>>>(img);
    wp_prep<<<(C_ * KCONV / 4 + 255) / 256, 256>>>(Wpatch);
    w1_prep<<<(NAG * C_ + 255) / 256, 256>>>(W1a, W1b);
    mask_kernel<<<(NE + 255) / 256, 256>>>(pos, out);
    w2h_kernel<<<64, 256>>>(W2, b2, Wp, bp, Wpv, bpv, Wr, br, Wrv, brv);
    // patch embedding GEMM (fp16 1-pass, K-chunk 64)
    patch_mma_kernel<<<dim3(NP / 128, C_ / 128), 256, P_SMEM>>>(bpatch);
    // a|g GEMM (fp16 2-pass, K-chunk 64)
    ag_mma_kernel<<<dim3(NP / 128, NAG / 128), 256, AG_SMEM>>>();
    // fused edge MLP + heads (one block per (b, i))
    edge_b_kernel<<<256, 512>>>(b1, out);
    // node_preds zeros
    int n0 = NE * 7 + NE;
    int cnt = out_size - n0;
    if (cnt > 0)
        zero_kernel<<<(cnt + 255) / 256, 256>>>(out, n0, out_size);
}

// round 10
// speedup vs baseline: 1.1394x; 1.1394x over previous
#include <cuda_runtime.h>
#include <cuda_bf16.h>
#include <cuda_fp16.h>
#include <cstdint>

#define B_    32
#define N_    8
#define CIN   3
#define HWD   224
#define PATCH 32
#define S_    49
#define C_    384
#define HM_   512
#define CO_   256
#define NP    12544
#define KCONV 3072
#define NE    2048
#define NAG   1024
#define NIMG  (B_*N_*CIN*HWD*HWD)

// ---- scratch (static device globals; no allocation) ----
__device__ __align__(16) __half g_img_h[NIMG];
__device__ __align__(16) __half g_Wph[C_ * KCONV];
__device__ __align__(16) __half g_W1t_h[NAG * C_];
__device__ __align__(16) __half g_feats_h[NP * C_];
__device__ __align__(16) __half g_feats_l[NP * C_];
__device__ float g_a[NP * HM_];
__device__ float g_g[NP * HM_];
__device__ float g_mask[NE];
__device__ float g_W2h[HM_ * 7];
__device__ float g_bias7[7];

// ---- helpers ----
__device__ __forceinline__ uint32_t smem_to_u32(const void* p) {
    uint32_t a;
    asm("{ .reg .u64 t; cvta.to.shared.u64 t, %1; cvt.u32.u64 %0, t; }" : "=r"(a) : "l"(p));
    return a;
}
__device__ __forceinline__ void cp16(uint32_t dst, const void* src) {
    asm volatile("cp.async.cg.shared.global [%0], [%1], 16;" :: "r"(dst), "l"(src));
}
#define CP_COMMIT() asm volatile("cp.async.commit_group;" ::: "memory")
#define CP_WAIT1()  asm volatile("cp.async.wait_group 1;" ::: "memory")
#define CP_WAIT0()  asm volatile("cp.async.wait_group 0;" ::: "memory")

__device__ __forceinline__ void ldm4(uint32_t* r, uint32_t addr) {
    asm volatile("ldmatrix.sync.aligned.m8n8.x4.shared.b16 {%0,%1,%2,%3}, [%4];"
                 : "=r"(r[0]), "=r"(r[1]), "=r"(r[2]), "=r"(r[3]) : "r"(addr));
}
__device__ __forceinline__ void mma_f16(float* c, const uint32_t* a,
                                        uint32_t b0, uint32_t b1) {
    asm volatile(
        "mma.sync.aligned.m16n8k16.row.col.f32.f16.f16.f32 "
        "{%0,%1,%2,%3}, {%4,%5,%6,%7}, {%8,%9}, {%0,%1,%2,%3};"
        : "+f"(c[0]), "+f"(c[1]), "+f"(c[2]), "+f"(c[3])
        : "r"(a[0]), "r"(a[1]), "r"(a[2]), "r"(a[3]), "r"(b0), "r"(b1));
}
__device__ __forceinline__ void hsplit2(float x, float y, uint32_t& hp, uint32_t& lp) {
    __half hx = __float2half_rn(x), hy = __float2half_rn(y);
    __half lx = __float2half_rn(x - __half2float(hx));
    __half ly = __float2half_rn(y - __half2float(hy));
    __half2 h(hx, hy), l(lx, ly);
    hp = *reinterpret_cast<uint32_t*>(&h);
    lp = *reinterpret_cast<uint32_t*>(&l);
}

// smem rows: 32 fp16 (64B) padded to 80B (conflict-free mod 128)
#define ROWB    80
#define TILE_B  (128 * ROWB)            /* 10240 */
// patch (1-pass fp16): A + B, 3 stages
#define P_STAGE  (2 * TILE_B)           /* 20480 */
#define P_SMEM   (3 * P_STAGE)          /* 61440 */
#define POFF_A   0
#define POFF_B   TILE_B
// ag (2-pass fp16): Ah + Al + Bh, 3 stages
#define AG_STAGE (3 * TILE_B)           /* 30720 */
#define AG_SMEM  (3 * AG_STAGE)         /* 92160 */
#define OFF_AH   0
#define OFF_AL   TILE_B
#define OFF_BH   (2 * TILE_B)

// ============================================================
// Prep kernels
// ============================================================
__global__ void img_prep(const float* __restrict__ img)
{
    long i8 = ((long)blockIdx.x * blockDim.x + threadIdx.x) * 8;
    if (i8 >= NIMG) return;
    float4 v0 = *(const float4*)&img[i8];
    float4 v1 = *(const float4*)&img[i8 + 4];
    __half2 a = __floats2half2_rn(v0.x, v0.y);
    __half2 b = __floats2half2_rn(v0.z, v0.w);
    __half2 c = __floats2half2_rn(v1.x, v1.y);
    __half2 d = __floats2half2_rn(v1.z, v1.w);
    *(uint4*)&g_img_h[i8] = make_uint4(*reinterpret_cast<uint32_t*>(&a),
                                       *reinterpret_cast<uint32_t*>(&b),
                                       *reinterpret_cast<uint32_t*>(&c),
                                       *reinterpret_cast<uint32_t*>(&d));
}

__global__ void wp_prep(const float* __restrict__ Wp)
{
    int i4 = blockIdx.x * blockDim.x + threadIdx.x;
    if (i4 >= C_ * KCONV / 4) return;
    float4 v = *(const float4*)&Wp[i4 * 4];
    __half2 a = __floats2half2_rn(v.x, v.y);
    __half2 b = __floats2half2_rn(v.z, v.w);
    *(uint2*)&g_Wph[i4 * 4] = make_uint2(*reinterpret_cast<uint32_t*>(&a),
                                         *reinterpret_cast<uint32_t*>(&b));
}

__global__ void w1_prep(const float* __restrict__ W1a, const float* __restrict__ W1b)
{
    int idx = blockIdx.x * blockDim.x + threadIdx.x;
    if (idx >= NAG * C_) return;
    int n = idx / C_, k = idx - n * C_;
    float v = (n < HM_) ? W1a[k * HM_ + n] : W1b[k * HM_ + (n - HM_)];
    g_W1t_h[idx] = __float2half_rn(v);
}

// ============================================================
// Patch GEMM: feats = im2row(img_h) x Wp^T, fp16 1-pass
// grid (98, 3), 256 thr, 60KB smem (3 stages), occ 2, K=3072 (96 chunks)
// ============================================================
__global__ void __launch_bounds__(256, 2)
patch_mma_kernel(const float* __restrict__ bp)
{
    extern __shared__ __align__(128) char smem[];
    const uint32_t sb = smem_to_u32(smem);
    const int tid = threadIdx.x, lane = tid & 31, w = tid >> 5;
    const int wm = w >> 2, wn = w & 3;
    const int bm = blockIdx.x * 128, bn = blockIdx.y * 128;

    // loaders: row = tid>>1, seg = tid&1 (16 fp16 = 32B each)
    const int lrow = tid >> 1, lseg = tid & 1;
    int abase;
    {
        int p  = bm + lrow;
        int n  = p / 49;
        int s  = p - n * 49;
        int py = s / 7, px = s - py * 7;
        abase = (n * CIN * HWD + py * PATCH) * HWD + px * PATCH + lseg * 16;
    }
    const long brow = (long)(bn + lrow) * KCONV + lseg * 16;

    float acc[4][4][4];
#pragma unroll
    for (int mi = 0; mi < 4; mi++)
#pragma unroll
        for (int ni = 0; ni < 4; ni++)
#pragma unroll
            for (int t = 0; t < 4; t++) acc[mi][ni][t] = 0.f;

    auto cpAB = [&](int c, int st) {
        int k  = c * 32;
        int ci = k >> 10, rem = k & 1023, y = rem >> 5;
        const __half* asrc = g_img_h + abase + ci * (HWD * HWD) + y * HWD;
        uint32_t ad = sb + st * P_STAGE + POFF_A + lrow * ROWB + lseg * 32;
        cp16(ad, asrc);
        cp16(ad + 16, asrc + 8);
        const __half* bsrc = g_Wph + brow + k;
        uint32_t bd = sb + st * P_STAGE + POFF_B + lrow * ROWB + lseg * 32;
        cp16(bd, bsrc);
        cp16(bd + 16, bsrc + 8);
    };

    const int NC = KCONV / 32;   // 96
    cpAB(0, 0); CP_COMMIT();
    cpAB(1, 1); CP_COMMIT();

    int st = 0;
#pragma unroll 1
    for (int c = 0; c < NC; c++) {
        if (c + 1 < NC) { CP_WAIT1(); } else { CP_WAIT0(); }
        __syncthreads();
        if (c + 2 < NC) {
            int st2 = st + 2; if (st2 >= 3) st2 -= 3;
            cpAB(c + 2, st2);
            CP_COMMIT();
        }
        {
            const uint32_t sbase = sb + st * P_STAGE;
#pragma unroll
            for (int step = 0; step < 2; step++) {
                const uint32_t co = (uint32_t)(step * 32 + (lane >> 4) * 16);
                uint32_t bf[2][4];
#pragma unroll
                for (int nj = 0; nj < 2; nj++) {
                    uint32_t ro = (uint32_t)((wn * 32 + nj * 16 + (lane & 15)) * ROWB) + co;
                    ldm4(bf[nj], sbase + POFF_B + ro);
                }
#pragma unroll
                for (int mi = 0; mi < 4; mi++) {
                    uint32_t af[4];
                    uint32_t ro = (uint32_t)((wm * 64 + mi * 16 + (lane & 15)) * ROWB) + co;
                    ldm4(af, sbase + POFF_A + ro);
#pragma unroll
                    for (int ni = 0; ni < 4; ni++) {
                        int nj = ni >> 1, o = ni & 1;
                        mma_f16(acc[mi][ni], af, bf[nj][o], bf[nj][o + 2]);
                    }
                }
            }
        }
        if (++st == 3) st = 0;
    }

    const int r  = lane >> 2;
    const int cc = (lane & 3) * 2;
#pragma unroll
    for (int mi = 0; mi < 4; mi++) {
#pragma unroll
        for (int ni = 0; ni < 4; ni++) {
            int m0  = bm + wm * 64 + mi * 16 + r;
            int col = bn + wn * 32 + ni * 8 + cc;
            float b0 = bp[col], b1 = bp[col + 1];
            uint32_t hp, lp;
            hsplit2(acc[mi][ni][0] + b0, acc[mi][ni][1] + b1, hp, lp);
            *(uint32_t*)&g_feats_h[(long)m0 * C_ + col] = hp;
            *(uint32_t*)&g_feats_l[(long)m0 * C_ + col] = lp;
            hsplit2(acc[mi][ni][2] + b0, acc[mi][ni][3] + b1, hp, lp);
            *(uint32_t*)&g_feats_h[(long)(m0 + 8) * C_ + col] = hp;
            *(uint32_t*)&g_feats_l[(long)(m0 + 8) * C_ + col] = lp;
        }
    }
}

// ============================================================
// a|g GEMM: [12544 x 1024] = feats x W1t^T, fp16 2-pass
// grid (98, 8), 90KB smem (3 stages), occ 2, K=384 (12 chunks)
// ============================================================
__global__ void __launch_bounds__(256, 2)
ag_mma_kernel()
{
    extern __shared__ __align__(128) char smem[];
    const uint32_t sb = smem_to_u32(smem);
    const int tid = threadIdx.x, lane = tid & 31, w = tid >> 5;
    const int wm = w >> 2, wn = w & 3;
    const int bm = blockIdx.x * 128, bn = blockIdx.y * 128;

    float acc[4][4][4];
#pragma unroll
    for (int mi = 0; mi < 4; mi++)
#pragma unroll
        for (int ni = 0; ni < 4; ni++)
#pragma unroll
            for (int t = 0; t < 4; t++) acc[mi][ni][t] = 0.f;

    auto cpAB = [&](int c, int st) {
        int kc = c * 32;
#pragma unroll
        for (int u = 0; u < 2; u++) {
            int idx = tid + u * 256;
            int row = idx >> 2, q = idx & 3;
            uint32_t base = sb + st * AG_STAGE + row * ROWB + q * 16;
            long ao = (long)(bm + row) * C_ + kc + q * 8;
            long bo = (long)(bn + row) * C_ + kc + q * 8;
            cp16(base + OFF_AH, &g_feats_h[ao]);
            cp16(base + OFF_AL, &g_feats_l[ao]);
            cp16(base + OFF_BH, &g_W1t_h[bo]);
        }
    };

    const int NC = C_ / 32;   // 12
    cpAB(0, 0); CP_COMMIT();
    cpAB(1, 1); CP_COMMIT();

    int st = 0;
#pragma unroll 1
    for (int c = 0; c < NC; c++) {
        if (c + 1 < NC) { CP_WAIT1(); } else { CP_WAIT0(); }
        __syncthreads();
        if (c + 2 < NC) {
            int st2 = st + 2; if (st2 >= 3) st2 -= 3;
            cpAB(c + 2, st2);
            CP_COMMIT();
        }
        {
            const uint32_t sbase = sb + st * AG_STAGE;
#pragma unroll
            for (int step = 0; step < 2; step++) {
                const uint32_t co = (uint32_t)(step * 32 + (lane >> 4) * 16);
                uint32_t bf[2][4];
#pragma unroll
                for (int nj = 0; nj < 2; nj++) {
                    uint32_t ro = (uint32_t)((wn * 32 + nj * 16 + (lane & 15)) * ROWB) + co;
                    ldm4(bf[nj], sbase + OFF_BH + ro);
                }
#pragma unroll
                for (int mi = 0; mi < 4; mi++) {
                    uint32_t afh[4], afl[4];
                    uint32_t ro = (uint32_t)((wm * 64 + mi * 16 + (lane & 15)) * ROWB) + co;
                    ldm4(afh, sbase + OFF_AH + ro);
                    ldm4(afl, sbase + OFF_AL + ro);
#pragma unroll
                    for (int ni = 0; ni < 4; ni++) {
                        int nj = ni >> 1, o = ni & 1;
                        mma_f16(acc[mi][ni], afh, bf[nj][o], bf[nj][o + 2]);
                        mma_f16(acc[mi][ni], afl, bf[nj][o], bf[nj][o + 2]);
                    }
                }
            }
        }
        if (++st == 3) st = 0;
    }

    float* dst = (bn < HM_) ? g_a : g_g;
    const int nb = (bn < HM_) ? bn : bn - HM_;
    const int r  = lane >> 2;
    const int cc = (lane & 3) * 2;
#pragma unroll
    for (int mi = 0; mi < 4; mi++) {
#pragma unroll
        for (int ni = 0; ni < 4; ni++) {
            int m0  = bm + wm * 64 + mi * 16 + r;
            int col = nb + wn * 32 + ni * 8 + cc;
            *(float2*)&dst[(long)m0 * HM_ + col] =
                make_float2(acc[mi][ni][0], acc[mi][ni][1]);
            *(float2*)&dst[(long)(m0 + 8) * HM_ + col] =
                make_float2(acc[mi][ni][2], acc[mi][ni][3]);
        }
    }
}

// ============================================================
// mask kernel
// ============================================================
__global__ void mask_kernel(const float* __restrict__ pos, float* __restrict__ out)
{
    int e = blockIdx.x * blockDim.x + threadIdx.x;
    if (e >= NE) return;
    int b = e >> 6, i = (e >> 3) & 7, j = e & 7;
    float xi = pos[(b * N_ + i) * 3 + 0], yi = pos[(b * N_ + i) * 3 + 1];
    float xj = pos[(b * N_ + j) * 3 + 0], yj = pos[(b * N_ + j) * 3 + 1];
    float dx = xi - xj, dy = yi - yj;
    float d2 = __fadd_rn(__fmul_rn(dx, dx), __fmul_rn(dy, dy));
    float m = (d2 < 0.25f && i != j) ? 1.0f : 0.0f;
    g_mask[e] = m;
    out[NE * 7 + e] = m;
}

// ============================================================
// w2h kernel: warp-per-h-row
// ============================================================
__device__ __forceinline__ float head_w(int o, int k,
                                        const float* Wph, const float* Wpv,
                                        const float* Wr, const float* Wrv)
{
    if (k < 2) return Wph[o * 2 + k];
    if (k < 4) return Wpv[o * 2 + (k - 2)];
    if (k < 6) return Wr[o * 2 + (k - 4)];
    return Wrv[o];
}

__global__ void __launch_bounds__(256)
w2h_kernel(const float* __restrict__ W2, const float* __restrict__ b2,
           const float* __restrict__ Wph, const float* __restrict__ bph,
           const float* __restrict__ Wpv, const float* __restrict__ bpv,
           const float* __restrict__ Wr,  const float* __restrict__ br,
           const float* __restrict__ Wrv, const float* __restrict__ brv)
{
    __shared__ float sW[CO_][7];
    const int tid = threadIdx.x, lane = tid & 31, wid = tid >> 5;

    if (tid < CO_) {
#pragma unroll
        for (int k = 0; k < 7; k++)
            sW[tid][k] = head_w(tid, k, Wph, Wpv, Wr, Wrv);
    }
    __syncthreads();

    const int h = blockIdx.x * 8 + wid;
    float acc[7] = {0, 0, 0, 0, 0, 0, 0};
#pragma unroll
    for (int t = 0; t < 8; t++) {
        int o = lane + 32 * t;
        float w2 = W2[h * CO_ + o];
#pragma unroll
        for (int k = 0; k < 7; k++)
            acc[k] = fmaf(w2, sW[o][k], acc[k]);
    }
#pragma unroll
    for (int k = 0; k < 7; k++) {
#pragma unroll
        for (int off = 16; off; off >>= 1)
            acc[k] += __shfl_down_sync(0xffffffffu, acc[k], off);
    }
    if (lane == 0) {
#pragma unroll
        for (int k = 0; k < 7; k++)
            g_W2h[h * 7 + k] = acc[k] * (1.0f / 49.0f);
    }

    if (blockIdx.x == 0 && tid < 7) {
        float sum = 0.f;
        for (int o = 0; o < CO_; o++)
            sum = fmaf(b2[o], sW[o][tid], sum);
        float bb = (tid < 2) ? bph[tid] : (tid < 4) ? bpv[tid - 2]
                 : (tid < 6) ? br[tid - 4] : brv[0];
        g_bias7[tid] = sum + bb;
    }
}

// ============================================================
// edge kernel: one block per (b, i); 512 threads (h = tid); 8 j-accums
// ============================================================
__global__ void __launch_bounds__(512, 2)
edge_b_kernel(const float* __restrict__ b1, float* __restrict__ out)
{
    __shared__ float red[16][28];
    __shared__ float sbias[7];

    const int blk = blockIdx.x;
    const int b   = blk >> 3;
    const int i   = blk & 7;
    const int tid = threadIdx.x, lane = tid & 31, wid = tid >> 5;

    if (tid < 7) sbias[tid] = g_bias7[tid];

    const float base = b1[tid];
    const float* __restrict__ ap = g_a + ((long)(b * 8 + i) * 49) * HM_ + tid;
    const float* __restrict__ gp = g_g + ((long)(b * 8) * 49) * HM_ + tid;

    float acc[8];
#pragma unroll
    for (int j = 0; j < 8; j++) acc[j] = 0.f;

#pragma unroll 1
    for (int s = 0; s < 49; s++) {
        const int so = s * HM_;
        float av = ap[so] + base;
        float gv[8];
#pragma unroll
        for (int j = 0; j < 8; j++)
            gv[j] = gp[j * (49 * HM_) + so];
#pragma unroll
        for (int j = 0; j < 8; j++)
            acc[j] += fmaxf(av + gv[j], 0.f);
    }

    float wv[7];
#pragma unroll
    for (int k = 0; k < 7; k++) wv[k] = g_W2h[tid * 7 + k];

    __syncthreads();

#pragma unroll 1
    for (int p0 = 0; p0 < 8; p0 += 4) {
        float pr[28];
#pragma unroll
        for (int q = 0; q < 4; q++)
#pragma unroll
            for (int k = 0; k < 7; k++)
                pr[q * 7 + k] = acc[p0 + q] * wv[k];
#pragma unroll
        for (int t = 0; t < 28; t++) {
#pragma unroll
            for (int off = 16; off; off >>= 1)
                pr[t] += __shfl_down_sync(0xffffffffu, pr[t], off);
        }
        if (lane == 0) {
#pragma unroll
            for (int t = 0; t < 28; t++) red[wid][t] = pr[t];
        }
        __syncthreads();
        if (tid < 28) {
            float v = 0.f;
#pragma unroll
            for (int ww = 0; ww < 16; ww++) v += red[ww][tid];
            int q = tid / 7, k = tid - 7 * q;
            int j = p0 + q;
            int e = b * 64 + i * 8 + j;
            float mf = g_mask[e];
            out[e * 7 + k] = (mf != 0.f) ? (v + sbias[k]) : 0.f;
        }
        __syncthreads();
    }
}

// ============================================================
// zero-fill node_preds section
// ============================================================
__global__ void zero_kernel(float* __restrict__ out, int n0, int n1)
{
    int idx = n0 + blockIdx.x * blockDim.x + threadIdx.x;
    if (idx < n1) out[idx] = 0.0f;
}

// ============================================================
extern "C" void kernel_launch(void* const* d_in, const int* in_sizes, int n_in,
                              void* d_out, int out_size)
{
    const float* img    = (const float*)d_in[0];
    const float* pos    = (const float*)d_in[1];
    /* d_in[2] = rot, unused */
    const float* Wpatch = (const float*)d_in[3];
    const float* bpatch = (const float*)d_in[4];
    const float* W1a    = (const float*)d_in[5];
    const float* W1b    = (const float*)d_in[6];
    const float* b1     = (const float*)d_in[7];
    const float* W2     = (const float*)d_in[8];
    const float* b2     = (const float*)d_in[9];
    const float* Wp     = (const float*)d_in[10];
    const float* bp     = (const float*)d_in[11];
    const float* Wpv    = (const float*)d_in[12];
    const float* bpv    = (const float*)d_in[13];
    const float* Wr     = (const float*)d_in[14];
    const float* br     = (const float*)d_in[15];
    const float* Wrv    = (const float*)d_in[16];
    const float* brv    = (const float*)d_in[17];
    float* out = (float*)d_out;

    cudaFuncSetAttribute(patch_mma_kernel,
                         cudaFuncAttributeMaxDynamicSharedMemorySize, P_SMEM);
    cudaFuncSetAttribute(ag_mma_kernel,
                         cudaFuncAttributeMaxDynamicSharedMemorySize, AG_SMEM);

    // independent prep
    img_prep<<<NIMG / (256 * 8), 256>>>(img);
    wp_prep<<<(C_ * KCONV / 4 + 255) / 256, 256>>>(Wpatch);
    w1_prep<<<(NAG * C_ + 255) / 256, 256>>>(W1a, W1b);
    mask_kernel<<<(NE + 255) / 256, 256>>>(pos, out);
    w2h_kernel<<<64, 256>>>(W2, b2, Wp, bp, Wpv, bpv, Wr, br, Wrv, brv);
    // patch embedding GEMM (fp16 1-pass, 3-stage pipeline)
    patch_mma_kernel<<<dim3(NP / 128, C_ / 128), 256, P_SMEM>>>(bpatch);
    // a|g GEMM (fp16 2-pass, 3-stage pipeline)
    ag_mma_kernel<<<dim3(NP / 128, NAG / 128), 256, AG_SMEM>>>();
    // fused edge MLP + heads (one block per (b, i))
    edge_b_kernel<<<256, 512>>>(b1, out);
    // node_preds zeros
    int n0 = NE * 7 + NE;
    int cnt = out_size - n0;
    if (cnt > 0)
        zero_kernel<<<(cnt + 255) / 256, 256>>>(out, n0, out_size);
}

// round 11
// speedup vs baseline: 1.3322x; 1.1692x over previous
#include <cuda_runtime.h>
#include <cuda_bf16.h>
#include <cuda_fp16.h>
#include <cstdint>

#define B_    32
#define N_    8
#define CIN   3
#define HWD   224
#define PATCH 32
#define S_    49
#define C_    384
#define HM_   512
#define CO_   256
#define NP    12544
#define KCONV 3072
#define NE    2048
#define NAG   1024
#define NIMG  (B_*N_*CIN*HWD*HWD)

// ---- scratch (static device globals; no allocation) ----
__device__ __align__(16) __half g_img_h[NIMG];
__device__ __align__(16) __half g_Wph[C_ * KCONV];
__device__ __align__(16) __half g_W1t_h[NAG * C_];
__device__ __align__(16) __half g_feats_h[NP * C_];
__device__ float g_a[NP * HM_];
__device__ float g_g[NP * HM_];
__device__ float g_mask[NE];
__device__ float g_W2h[HM_ * 7];
__device__ float g_bias7[7];

// ---- helpers ----
__device__ __forceinline__ uint32_t smem_to_u32(const void* p) {
    uint32_t a;
    asm("{ .reg .u64 t; cvta.to.shared.u64 t, %1; cvt.u32.u64 %0, t; }" : "=r"(a) : "l"(p));
    return a;
}
__device__ __forceinline__ void cp16(uint32_t dst, const void* src) {
    asm volatile("cp.async.cg.shared.global [%0], [%1], 16;" :: "r"(dst), "l"(src));
}
#define CP_COMMIT() asm volatile("cp.async.commit_group;" ::: "memory")
#define CP_WAIT1()  asm volatile("cp.async.wait_group 1;" ::: "memory")
#define CP_WAIT0()  asm volatile("cp.async.wait_group 0;" ::: "memory")

__device__ __forceinline__ void ldm4(uint32_t* r, uint32_t addr) {
    asm volatile("ldmatrix.sync.aligned.m8n8.x4.shared.b16 {%0,%1,%2,%3}, [%4];"
                 : "=r"(r[0]), "=r"(r[1]), "=r"(r[2]), "=r"(r[3]) : "r"(addr));
}
__device__ __forceinline__ void mma_f16(float* c, const uint32_t* a,
                                        uint32_t b0, uint32_t b1) {
    asm volatile(
        "mma.sync.aligned.m16n8k16.row.col.f32.f16.f16.f32 "
        "{%0,%1,%2,%3}, {%4,%5,%6,%7}, {%8,%9}, {%0,%1,%2,%3};"
        : "+f"(c[0]), "+f"(c[1]), "+f"(c[2]), "+f"(c[3])
        : "r"(a[0]), "r"(a[1]), "r"(a[2]), "r"(a[3]), "r"(b0), "r"(b1));
}
__device__ __forceinline__ uint32_t h2pack(float x, float y) {
    __half2 h = __floats2half2_rn(x, y);
    return *reinterpret_cast<uint32_t*>(&h);
}

// smem rows: 32 fp16 (64B) padded to 80B (conflict-free mod 128)
#define ROWB    80
#define TILE_B  (128 * ROWB)            /* 10240 */
// both GEMMs (1-pass fp16): A + B per stage, 3 stages
#define G_STAGE  (2 * TILE_B)           /* 20480 */
#define G_SMEM   (3 * G_STAGE)          /* 61440 */
#define GOFF_A   0
#define GOFF_B   TILE_B

// ============================================================
// Fused prep kernel: w2h | mask | wp | w1 | img  (one launch)
// ============================================================
#define PB_W2H  64
#define PB_MASK 8
#define PB_WP   ((C_ * KCONV / 4) / 256)     /* 1152 */
#define PB_W1   ((NAG * C_) / 256)           /* 1536 */
#define PB_IMG  (NIMG / (256 * 8))           /* 18816 */
#define PB_TOTAL (PB_W2H + PB_MASK + PB_WP + PB_W1 + PB_IMG)

__device__ __forceinline__ float head_w(int o, int k,
                                        const float* Wph, const float* Wpv,
                                        const float* Wr, const float* Wrv)
{
    if (k < 2) return Wph[o * 2 + k];
    if (k < 4) return Wpv[o * 2 + (k - 2)];
    if (k < 6) return Wr[o * 2 + (k - 4)];
    return Wrv[o];
}

__global__ void __launch_bounds__(256)
prep_all_kernel(const float* __restrict__ img, const float* __restrict__ pos,
                const float* __restrict__ Wp,
                const float* __restrict__ W1a, const float* __restrict__ W1b,
                const float* __restrict__ W2,  const float* __restrict__ b2,
                const float* __restrict__ Wph, const float* __restrict__ bph,
                const float* __restrict__ Wpv, const float* __restrict__ bpv,
                const float* __restrict__ Wr,  const float* __restrict__ br,
                const float* __restrict__ Wrv, const float* __restrict__ brv,
                float* __restrict__ out)
{
    __shared__ float sW[CO_][7];
    int bid = blockIdx.x;
    const int tid = threadIdx.x;

    if (bid < PB_W2H) {
        // ---- w2h: warp-per-h-row ----
        const int lane = tid & 31, wid = tid >> 5;
        if (tid < CO_) {
#pragma unroll
            for (int k = 0; k < 7; k++)
                sW[tid][k] = head_w(tid, k, Wph, Wpv, Wr, Wrv);
        }
        __syncthreads();
        const int h = bid * 8 + wid;
        float acc[7] = {0, 0, 0, 0, 0, 0, 0};
#pragma unroll
        for (int t = 0; t < 8; t++) {
            int o = lane + 32 * t;
            float w2 = W2[h * CO_ + o];
#pragma unroll
            for (int k = 0; k < 7; k++)
                acc[k] = fmaf(w2, sW[o][k], acc[k]);
        }
#pragma unroll
        for (int k = 0; k < 7; k++) {
#pragma unroll
            for (int off = 16; off; off >>= 1)
                acc[k] += __shfl_down_sync(0xffffffffu, acc[k], off);
        }
        if (lane == 0) {
#pragma unroll
            for (int k = 0; k < 7; k++)
                g_W2h[h * 7 + k] = acc[k] * (1.0f / 49.0f);
        }
        if (bid == 0 && tid < 7) {
            float sum = 0.f;
            for (int o = 0; o < CO_; o++)
                sum = fmaf(b2[o], sW[o][tid], sum);
            float bb = (tid < 2) ? bph[tid] : (tid < 4) ? bpv[tid - 2]
                     : (tid < 6) ? br[tid - 4] : brv[0];
            g_bias7[tid] = sum + bb;
        }
        return;
    }
    bid -= PB_W2H;

    if (bid < PB_MASK) {
        int e = bid * 256 + tid;
        int b = e >> 6, i = (e >> 3) & 7, j = e & 7;
        float xi = pos[(b * N_ + i) * 3 + 0], yi = pos[(b * N_ + i) * 3 + 1];
        float xj = pos[(b * N_ + j) * 3 + 0], yj = pos[(b * N_ + j) * 3 + 1];
        float dx = xi - xj, dy = yi - yj;
        float d2 = __fadd_rn(__fmul_rn(dx, dx), __fmul_rn(dy, dy));
        float m = (d2 < 0.25f && i != j) ? 1.0f : 0.0f;
        g_mask[e] = m;
        out[NE * 7 + e] = m;
        return;
    }
    bid -= PB_MASK;

    if (bid < PB_WP) {
        int i4 = bid * 256 + tid;
        float4 v = *(const float4*)&Wp[(long)i4 * 4];
        *(uint2*)&g_Wph[(long)i4 * 4] = make_uint2(h2pack(v.x, v.y), h2pack(v.z, v.w));
        return;
    }
    bid -= PB_WP;

    if (bid < PB_W1) {
        int idx = bid * 256 + tid;
        int n = idx / C_, k = idx - n * C_;
        float v = (n < HM_) ? W1a[k * HM_ + n] : W1b[k * HM_ + (n - HM_)];
        g_W1t_h[idx] = __float2half_rn(v);
        return;
    }
    bid -= PB_W1;

    {   // ---- img fp32 -> fp16 ----
        long i8 = ((long)bid * 256 + tid) * 8;
        float4 v0 = *(const float4*)&img[i8];
        float4 v1 = *(const float4*)&img[i8 + 4];
        *(uint4*)&g_img_h[i8] = make_uint4(h2pack(v0.x, v0.y), h2pack(v0.z, v0.w),
                                           h2pack(v1.x, v1.y), h2pack(v1.z, v1.w));
    }
}

// ============================================================
// Patch GEMM: feats = im2row(img_h) x Wp^T, fp16 1-pass
// grid (3, 98) — bn fastest for img L2 reuse. 3-stage pipeline.
// ============================================================
__global__ void __launch_bounds__(256, 2)
patch_mma_kernel(const float* __restrict__ bp)
{
    extern __shared__ __align__(128) char smem[];
    const uint32_t sb = smem_to_u32(smem);
    const int tid = threadIdx.x, lane = tid & 31, w = tid >> 5;
    const int wm = w >> 2, wn = w & 3;
    const int bn = blockIdx.x * 128, bm = blockIdx.y * 128;

    const int lrow = tid >> 1, lseg = tid & 1;
    int abase;
    {
        int p  = bm + lrow;
        int n  = p / 49;
        int s  = p - n * 49;
        int py = s / 7, px = s - py * 7;
        abase = (n * CIN * HWD + py * PATCH) * HWD + px * PATCH + lseg * 16;
    }
    const long brow = (long)(bn + lrow) * KCONV + lseg * 16;

    float acc[4][4][4];
#pragma unroll
    for (int mi = 0; mi < 4; mi++)
#pragma unroll
        for (int ni = 0; ni < 4; ni++)
#pragma unroll
            for (int t = 0; t < 4; t++) acc[mi][ni][t] = 0.f;

    auto cpAB = [&](int c, int st) {
        int k  = c * 32;
        int ci = k >> 10, rem = k & 1023, y = rem >> 5;
        const __half* asrc = g_img_h + abase + ci * (HWD * HWD) + y * HWD;
        uint32_t ad = sb + st * G_STAGE + GOFF_A + lrow * ROWB + lseg * 32;
        cp16(ad, asrc);
        cp16(ad + 16, asrc + 8);
        const __half* bsrc = g_Wph + brow + k;
        uint32_t bd = sb + st * G_STAGE + GOFF_B + lrow * ROWB + lseg * 32;
        cp16(bd, bsrc);
        cp16(bd + 16, bsrc + 8);
    };

    const int NC = KCONV / 32;   // 96
    cpAB(0, 0); CP_COMMIT();
    cpAB(1, 1); CP_COMMIT();

    int st = 0;
#pragma unroll 1
    for (int c = 0; c < NC; c++) {
        if (c + 1 < NC) { CP_WAIT1(); } else { CP_WAIT0(); }
        __syncthreads();
        if (c + 2 < NC) {
            int st2 = st + 2; if (st2 >= 3) st2 -= 3;
            cpAB(c + 2, st2);
            CP_COMMIT();
        }
        {
            const uint32_t sbase = sb + st * G_STAGE;
#pragma unroll
            for (int step = 0; step < 2; step++) {
                const uint32_t co = (uint32_t)(step * 32 + (lane >> 4) * 16);
                uint32_t bf[2][4];
#pragma unroll
                for (int nj = 0; nj < 2; nj++) {
                    uint32_t ro = (uint32_t)((wn * 32 + nj * 16 + (lane & 15)) * ROWB) + co;
                    ldm4(bf[nj], sbase + GOFF_B + ro);
                }
#pragma unroll
                for (int mi = 0; mi < 4; mi++) {
                    uint32_t af[4];
                    uint32_t ro = (uint32_t)((wm * 64 + mi * 16 + (lane & 15)) * ROWB) + co;
                    ldm4(af, sbase + GOFF_A + ro);
#pragma unroll
                    for (int ni = 0; ni < 4; ni++) {
                        int nj = ni >> 1, o = ni & 1;
                        mma_f16(acc[mi][ni], af, bf[nj][o], bf[nj][o + 2]);
                    }
                }
            }
        }
        if (++st == 3) st = 0;
    }

    const int r  = lane >> 2;
    const int cc = (lane & 3) * 2;
#pragma unroll
    for (int mi = 0; mi < 4; mi++) {
#pragma unroll
        for (int ni = 0; ni < 4; ni++) {
            int m0  = bm + wm * 64 + mi * 16 + r;
            int col = bn + wn * 32 + ni * 8 + cc;
            float b0 = bp[col], b1 = bp[col + 1];
            *(uint32_t*)&g_feats_h[(long)m0 * C_ + col] =
                h2pack(acc[mi][ni][0] + b0, acc[mi][ni][1] + b1);
            *(uint32_t*)&g_feats_h[(long)(m0 + 8) * C_ + col] =
                h2pack(acc[mi][ni][2] + b0, acc[mi][ni][3] + b1);
        }
    }
}

// ============================================================
// a|g GEMM: [12544 x 1024] = feats_h x W1t^T, fp16 1-pass
// grid (8, 98) — bn fastest for feats L2 reuse. 3-stage pipeline.
// ============================================================
__global__ void __launch_bounds__(256, 2)
ag_mma_kernel()
{
    extern __shared__ __align__(128) char smem[];
    const uint32_t sb = smem_to_u32(smem);
    const int tid = threadIdx.x, lane = tid & 31, w = tid >> 5;
    const int wm = w >> 2, wn = w & 3;
    const int bn = blockIdx.x * 128, bm = blockIdx.y * 128;

    const int lrow = tid >> 1, lseg = tid & 1;
    const long arow = (long)(bm + lrow) * C_ + lseg * 16;
    const long brow = (long)(bn + lrow) * C_ + lseg * 16;

    float acc[4][4][4];
#pragma unroll
    for (int mi = 0; mi < 4; mi++)
#pragma unroll
        for (int ni = 0; ni < 4; ni++)
#pragma unroll
            for (int t = 0; t < 4; t++) acc[mi][ni][t] = 0.f;

    auto cpAB = [&](int c, int st) {
        int k = c * 32;
        const __half* asrc = g_feats_h + arow + k;
        uint32_t ad = sb + st * G_STAGE + GOFF_A + lrow * ROWB + lseg * 32;
        cp16(ad, asrc);
        cp16(ad + 16, asrc + 8);
        const __half* bsrc = g_W1t_h + brow + k;
        uint32_t bd = sb + st * G_STAGE + GOFF_B + lrow * ROWB + lseg * 32;
        cp16(bd, bsrc);
        cp16(bd + 16, bsrc + 8);
    };

    const int NC = C_ / 32;   // 12
    cpAB(0, 0); CP_COMMIT();
    cpAB(1, 1); CP_COMMIT();

    int st = 0;
#pragma unroll 1
    for (int c = 0; c < NC; c++) {
        if (c + 1 < NC) { CP_WAIT1(); } else { CP_WAIT0(); }
        __syncthreads();
        if (c + 2 < NC) {
            int st2 = st + 2; if (st2 >= 3) st2 -= 3;
            cpAB(c + 2, st2);
            CP_COMMIT();
        }
        {
            const uint32_t sbase = sb + st * G_STAGE;
#pragma unroll
            for (int step = 0; step < 2; step++) {
                const uint32_t co = (uint32_t)(step * 32 + (lane >> 4) * 16);
                uint32_t bf[2][4];
#pragma unroll
                for (int nj = 0; nj < 2; nj++) {
                    uint32_t ro = (uint32_t)((wn * 32 + nj * 16 + (lane & 15)) * ROWB) + co;
                    ldm4(bf[nj], sbase + GOFF_B + ro);
                }
#pragma unroll
                for (int mi = 0; mi < 4; mi++) {
                    uint32_t af[4];
                    uint32_t ro = (uint32_t)((wm * 64 + mi * 16 + (lane & 15)) * ROWB) + co;
                    ldm4(af, sbase + GOFF_A + ro);
#pragma unroll
                    for (int ni = 0; ni < 4; ni++) {
                        int nj = ni >> 1, o = ni & 1;
                        mma_f16(acc[mi][ni], af, bf[nj][o], bf[nj][o + 2]);
                    }
                }
            }
        }
        if (++st == 3) st = 0;
    }

    float* dst = (bn < HM_) ? g_a : g_g;
    const int nb = (bn < HM_) ? bn : bn - HM_;
    const int r  = lane >> 2;
    const int cc = (lane & 3) * 2;
#pragma unroll
    for (int mi = 0; mi < 4; mi++) {
#pragma unroll
        for (int ni = 0; ni < 4; ni++) {
            int m0  = bm + wm * 64 + mi * 16 + r;
            int col = nb + wn * 32 + ni * 8 + cc;
            *(float2*)&dst[(long)m0 * HM_ + col] =
                make_float2(acc[mi][ni][0], acc[mi][ni][1]);
            *(float2*)&dst[(long)(m0 + 8) * HM_ + col] =
                make_float2(acc[mi][ni][2], acc[mi][ni][3]);
        }
    }
}

// ============================================================
// edge kernel: one block per (b, i); 512 threads (h = tid); 8 j-accums
// ============================================================
__global__ void __launch_bounds__(512, 2)
edge_b_kernel(const float* __restrict__ b1, float* __restrict__ out)
{
    __shared__ float red[16][28];
    __shared__ float sbias[7];

    const int blk = blockIdx.x;
    const int b   = blk >> 3;
    const int i   = blk & 7;
    const int tid = threadIdx.x, lane = tid & 31, wid = tid >> 5;

    if (tid < 7) sbias[tid] = g_bias7[tid];

    const float base = b1[tid];
    const float* __restrict__ ap = g_a + ((long)(b * 8 + i) * 49) * HM_ + tid;
    const float* __restrict__ gp = g_g + ((long)(b * 8) * 49) * HM_ + tid;

    float acc[8];
#pragma unroll
    for (int j = 0; j < 8; j++) acc[j] = 0.f;

#pragma unroll 1
    for (int s = 0; s < 49; s++) {
        const int so = s * HM_;
        float av = ap[so] + base;
        float gv[8];
#pragma unroll
        for (int j = 0; j < 8; j++)
            gv[j] = gp[j * (49 * HM_) + so];
#pragma unroll
        for (int j = 0; j < 8; j++)
            acc[j] += fmaxf(av + gv[j], 0.f);
    }

    float wv[7];
#pragma unroll
    for (int k = 0; k < 7; k++) wv[k] = g_W2h[tid * 7 + k];

    __syncthreads();

#pragma unroll 1
    for (int p0 = 0; p0 < 8; p0 += 4) {
        float pr[28];
#pragma unroll
        for (int q = 0; q < 4; q++)
#pragma unroll
            for (int k = 0; k < 7; k++)
                pr[q * 7 + k] = acc[p0 + q] * wv[k];
#pragma unroll
        for (int t = 0; t < 28; t++) {
#pragma unroll
            for (int off = 16; off; off >>= 1)
                pr[t] += __shfl_down_sync(0xffffffffu, pr[t], off);
        }
        if (lane == 0) {
#pragma unroll
            for (int t = 0; t < 28; t++) red[wid][t] = pr[t];
        }
        __syncthreads();
        if (tid < 28) {
            float v = 0.f;
#pragma unroll
            for (int ww = 0; ww < 16; ww++) v += red[ww][tid];
            int q = tid / 7, k = tid - 7 * q;
            int j = p0 + q;
            int e = b * 64 + i * 8 + j;
            float mf = g_mask[e];
            out[e * 7 + k] = (mf != 0.f) ? (v + sbias[k]) : 0.f;
        }
        __syncthreads();
    }
}

// ============================================================
// zero-fill node_preds section
// ============================================================
__global__ void zero_kernel(float* __restrict__ out, int n0, int n1)
{
    int idx = n0 + blockIdx.x * blockDim.x + threadIdx.x;
    if (idx < n1) out[idx] = 0.0f;
}

// ============================================================
extern "C" void kernel_launch(void* const* d_in, const int* in_sizes, int n_in,
                              void* d_out, int out_size)
{
    const float* img    = (const float*)d_in[0];
    const float* pos    = (const float*)d_in[1];
    /* d_in[2] = rot, unused */
    const float* Wpatch = (const float*)d_in[3];
    const float* bpatch = (const float*)d_in[4];
    const float* W1a    = (const float*)d_in[5];
    const float* W1b    = (const float*)d_in[6];
    const float* b1     = (const float*)d_in[7];
    const float* W2     = (const float*)d_in[8];
    const float* b2     = (const float*)d_in[9];
    const float* Wp     = (const float*)d_in[10];
    const float* bp     = (const float*)d_in[11];
    const float* Wpv    = (const float*)d_in[12];
    const float* bpv    = (const float*)d_in[13];
    const float* Wr     = (const float*)d_in[14];
    const float* br     = (const float*)d_in[15];
    const float* Wrv    = (const float*)d_in[16];
    const float* brv    = (const float*)d_in[17];
    float* out = (float*)d_out;

    cudaFuncSetAttribute(patch_mma_kernel,
                         cudaFuncAttributeMaxDynamicSharedMemorySize, G_SMEM);
    cudaFuncSetAttribute(ag_mma_kernel,
                         cudaFuncAttributeMaxDynamicSharedMemorySize, G_SMEM);

    // fused prep: w2h | mask | Wp->fp16 | W1->fp16^T | img->fp16
    prep_all_kernel<<<PB_TOTAL, 256>>>(img, pos, Wpatch, W1a, W1b, W2, b2,
                                       Wp, bp, Wpv, bpv, Wr, br, Wrv, brv, out);
    // patch embedding GEMM (fp16 1-pass, 3-stage, bn-fastest grid)
    patch_mma_kernel<<<dim3(C_ / 128, NP / 128), 256, G_SMEM>>>(bpatch);
    // a|g GEMM (fp16 1-pass, 3-stage, bn-fastest grid)
    ag_mma_kernel<<<dim3(NAG / 128, NP / 128), 256, G_SMEM>>>();
    // fused edge MLP + heads
    edge_b_kernel<<<256, 512>>>(b1, out);
    // node_preds zeros
    int n0 = NE * 7 + NE;
    int cnt = out_size - n0;
    if (cnt > 0)
        zero_kernel<<<(cnt + 255) / 256, 256>>>(out, n0, out_size);
}

// round 12
// speedup vs baseline: 1.4320x; 1.0749x over previous
#include <cuda_runtime.h>
#include <cuda_bf16.h>
#include <cuda_fp16.h>
#include <cstdint>

#define B_    32
#define N_    8
#define CIN   3
#define HWD   224
#define PATCH 32
#define S_    49
#define C_    384
#define HM_   512
#define CO_   256
#define NP    12544
#define KCONV 3072
#define NE    2048
#define NAG   1024
#define NIMG  (B_*N_*CIN*HWD*HWD)
#define NODE0 (NE * 7 + NE)        /* 16384 */
#define NODEZ (B_ * N_ * 3600)     /* 921600 */

// ---- scratch (static device globals; no allocation) ----
__device__ __align__(16) __half g_img_h[NIMG];
__device__ __align__(16) __half g_Wph[C_ * KCONV];
__device__ __align__(16) __half g_W1t_h[NAG * C_];
__device__ __align__(16) __half g_feats_h[NP * C_];
__device__ __align__(16) __half g_a[NP * HM_];     // includes +b1
__device__ __align__(16) __half g_g[NP * HM_];
__device__ float g_mask[NE];
__device__ float g_W2h[HM_ * 7];
__device__ float g_bias7[7];

// ---- helpers ----
__device__ __forceinline__ uint32_t smem_to_u32(const void* p) {
    uint32_t a;
    asm("{ .reg .u64 t; cvta.to.shared.u64 t, %1; cvt.u32.u64 %0, t; }" : "=r"(a) : "l"(p));
    return a;
}
__device__ __forceinline__ void cp16(uint32_t dst, const void* src) {
    asm volatile("cp.async.cg.shared.global [%0], [%1], 16;" :: "r"(dst), "l"(src));
}
#define CP_COMMIT() asm volatile("cp.async.commit_group;" ::: "memory")
#define CP_WAIT1()  asm volatile("cp.async.wait_group 1;" ::: "memory")
#define CP_WAIT0()  asm volatile("cp.async.wait_group 0;" ::: "memory")

__device__ __forceinline__ void ldm4(uint32_t* r, uint32_t addr) {
    asm volatile("ldmatrix.sync.aligned.m8n8.x4.shared.b16 {%0,%1,%2,%3}, [%4];"
                 : "=r"(r[0]), "=r"(r[1]), "=r"(r[2]), "=r"(r[3]) : "r"(addr));
}
__device__ __forceinline__ void mma_f16(float* c, const uint32_t* a,
                                        uint32_t b0, uint32_t b1) {
    asm volatile(
        "mma.sync.aligned.m16n8k16.row.col.f32.f16.f16.f32 "
        "{%0,%1,%2,%3}, {%4,%5,%6,%7}, {%8,%9}, {%0,%1,%2,%3};"
        : "+f"(c[0]), "+f"(c[1]), "+f"(c[2]), "+f"(c[3])
        : "r"(a[0]), "r"(a[1]), "r"(a[2]), "r"(a[3]), "r"(b0), "r"(b1));
}
__device__ __forceinline__ uint32_t h2pack(float x, float y) {
    __half2 h = __floats2half2_rn(x, y);
    return *reinterpret_cast<uint32_t*>(&h);
}

// smem rows: 32 fp16 (64B) padded to 80B (conflict-free mod 128)
#define ROWB    80
#define TILE_B  (128 * ROWB)
#define G_STAGE  (2 * TILE_B)
#define G_SMEM   (3 * G_STAGE)
#define GOFF_A   0
#define GOFF_B   TILE_B

// ============================================================
// Fused prep kernel: w2h | mask | wp | w1 | img | node-zeros
// ============================================================
#define PB_W2H  64
#define PB_MASK 8
#define PB_WP   ((C_ * KCONV / 4) / 256)
#define PB_W1   ((NAG * C_) / 256)
#define PB_IMG  (NIMG / (256 * 8))
#define PB_ZERO (NODEZ / (256 * 16))         /* 225 */
#define PB_TOTAL (PB_W2H + PB_MASK + PB_WP + PB_W1 + PB_IMG + PB_ZERO)

__device__ __forceinline__ float head_w(int o, int k,
                                        const float* Wph, const float* Wpv,
                                        const float* Wr, const float* Wrv)
{
    if (k < 2) return Wph[o * 2 + k];
    if (k < 4) return Wpv[o * 2 + (k - 2)];
    if (k < 6) return Wr[o * 2 + (k - 4)];
    return Wrv[o];
}

__global__ void __launch_bounds__(256)
prep_all_kernel(const float* __restrict__ img, const float* __restrict__ pos,
                const float* __restrict__ Wp,
                const float* __restrict__ W1a, const float* __restrict__ W1b,
                const float* __restrict__ W2,  const float* __restrict__ b2,
                const float* __restrict__ Wph, const float* __restrict__ bph,
                const float* __restrict__ Wpv, const float* __restrict__ bpv,
                const float* __restrict__ Wr,  const float* __restrict__ br,
                const float* __restrict__ Wrv, const float* __restrict__ brv,
                float* __restrict__ out)
{
    __shared__ float sW[CO_][7];
    int bid = blockIdx.x;
    const int tid = threadIdx.x;

    if (bid < PB_W2H) {
        const int lane = tid & 31, wid = tid >> 5;
        if (tid < CO_) {
#pragma unroll
            for (int k = 0; k < 7; k++)
                sW[tid][k] = head_w(tid, k, Wph, Wpv, Wr, Wrv);
        }
        __syncthreads();
        const int h = bid * 8 + wid;
        float acc[7] = {0, 0, 0, 0, 0, 0, 0};
#pragma unroll
        for (int t = 0; t < 8; t++) {
            int o = lane + 32 * t;
            float w2 = W2[h * CO_ + o];
#pragma unroll
            for (int k = 0; k < 7; k++)
                acc[k] = fmaf(w2, sW[o][k], acc[k]);
        }
#pragma unroll
        for (int k = 0; k < 7; k++) {
#pragma unroll
            for (int off = 16; off; off >>= 1)
                acc[k] += __shfl_down_sync(0xffffffffu, acc[k], off);
        }
        if (lane == 0) {
#pragma unroll
            for (int k = 0; k < 7; k++)
                g_W2h[h * 7 + k] = acc[k] * (1.0f / 49.0f);
        }
        if (bid == 0 && tid < 7) {
            float sum = 0.f;
            for (int o = 0; o < CO_; o++)
                sum = fmaf(b2[o], sW[o][tid], sum);
            float bb = (tid < 2) ? bph[tid] : (tid < 4) ? bpv[tid - 2]
                     : (tid < 6) ? br[tid - 4] : brv[0];
            g_bias7[tid] = sum + bb;
        }
        return;
    }
    bid -= PB_W2H;

    if (bid < PB_MASK) {
        int e = bid * 256 + tid;
        int b = e >> 6, i = (e >> 3) & 7, j = e & 7;
        float xi = pos[(b * N_ + i) * 3 + 0], yi = pos[(b * N_ + i) * 3 + 1];
        float xj = pos[(b * N_ + j) * 3 + 0], yj = pos[(b * N_ + j) * 3 + 1];
        float dx = xi - xj, dy = yi - yj;
        float d2 = __fadd_rn(__fmul_rn(dx, dx), __fmul_rn(dy, dy));
        float m = (d2 < 0.25f && i != j) ? 1.0f : 0.0f;
        g_mask[e] = m;
        out[NE * 7 + e] = m;
        return;
    }
    bid -= PB_MASK;

    if (bid < PB_WP) {
        int i4 = bid * 256 + tid;
        float4 v = *(const float4*)&Wp[(long)i4 * 4];
        *(uint2*)&g_Wph[(long)i4 * 4] = make_uint2(h2pack(v.x, v.y), h2pack(v.z, v.w));
        return;
    }
    bid -= PB_WP;

    if (bid < PB_W1) {
        int idx = bid * 256 + tid;
        int n = idx / C_, k = idx - n * C_;
        float v = (n < HM_) ? W1a[k * HM_ + n] : W1b[k * HM_ + (n - HM_)];
        g_W1t_h[idx] = __float2half_rn(v);
        return;
    }
    bid -= PB_W1;

    if (bid < PB_IMG) {
        long i8 = ((long)bid * 256 + tid) * 8;
        float4 v0 = *(const float4*)&img[i8];
        float4 v1 = *(const float4*)&img[i8 + 4];
        *(uint4*)&g_img_h[i8] = make_uint4(h2pack(v0.x, v0.y), h2pack(v0.z, v0.w),
                                           h2pack(v1.x, v1.y), h2pack(v1.z, v1.w));
        return;
    }
    bid -= PB_IMG;

    {   // ---- node_preds zeros: 16 floats / thread ----
        int base = NODE0 + (bid * 256 + tid) * 16;
        float4 z = make_float4(0.f, 0.f, 0.f, 0.f);
        *(float4*)&out[base]      = z;
        *(float4*)&out[base + 4]  = z;
        *(float4*)&out[base + 8]  = z;
        *(float4*)&out[base + 12] = z;
    }
}

// ============================================================
// Patch GEMM: feats = im2row(img_h) x Wp^T, fp16 1-pass, 3-stage
// grid (3, 98) — bn fastest for img L2 reuse
// ============================================================
__global__ void __launch_bounds__(256, 2)
patch_mma_kernel(const float* __restrict__ bp)
{
    extern __shared__ __align__(128) char smem[];
    const uint32_t sb = smem_to_u32(smem);
    const int tid = threadIdx.x, lane = tid & 31, w = tid >> 5;
    const int wm = w >> 2, wn = w & 3;
    const int bn = blockIdx.x * 128, bm = blockIdx.y * 128;

    const int lrow = tid >> 1, lseg = tid & 1;
    int abase;
    {
        int p  = bm + lrow;
        int n  = p / 49;
        int s  = p - n * 49;
        int py = s / 7, px = s - py * 7;
        abase = (n * CIN * HWD + py * PATCH) * HWD + px * PATCH + lseg * 16;
    }
    const long brow = (long)(bn + lrow) * KCONV + lseg * 16;

    float acc[4][4][4];
#pragma unroll
    for (int mi = 0; mi < 4; mi++)
#pragma unroll
        for (int ni = 0; ni < 4; ni++)
#pragma unroll
            for (int t = 0; t < 4; t++) acc[mi][ni][t] = 0.f;

    auto cpAB = [&](int c, int st) {
        int k  = c * 32;
        int ci = k >> 10, rem = k & 1023, y = rem >> 5;
        const __half* asrc = g_img_h + abase + ci * (HWD * HWD) + y * HWD;
        uint32_t ad = sb + st * G_STAGE + GOFF_A + lrow * ROWB + lseg * 32;
        cp16(ad, asrc);
        cp16(ad + 16, asrc + 8);
        const __half* bsrc = g_Wph + brow + k;
        uint32_t bd = sb + st * G_STAGE + GOFF_B + lrow * ROWB + lseg * 32;
        cp16(bd, bsrc);
        cp16(bd + 16, bsrc + 8);
    };

    const int NC = KCONV / 32;   // 96
    cpAB(0, 0); CP_COMMIT();
    cpAB(1, 1); CP_COMMIT();

    int st = 0;
#pragma unroll 1
    for (int c = 0; c < NC; c++) {
        if (c + 1 < NC) { CP_WAIT1(); } else { CP_WAIT0(); }
        __syncthreads();
        if (c + 2 < NC) {
            int st2 = st + 2; if (st2 >= 3) st2 -= 3;
            cpAB(c + 2, st2);
            CP_COMMIT();
        }
        {
            const uint32_t sbase = sb + st * G_STAGE;
#pragma unroll
            for (int step = 0; step < 2; step++) {
                const uint32_t co = (uint32_t)(step * 32 + (lane >> 4) * 16);
                uint32_t bf[2][4];
#pragma unroll
                for (int nj = 0; nj < 2; nj++) {
                    uint32_t ro = (uint32_t)((wn * 32 + nj * 16 + (lane & 15)) * ROWB) + co;
                    ldm4(bf[nj], sbase + GOFF_B + ro);
                }
#pragma unroll
                for (int mi = 0; mi < 4; mi++) {
                    uint32_t af[4];
                    uint32_t ro = (uint32_t)((wm * 64 + mi * 16 + (lane & 15)) * ROWB) + co;
                    ldm4(af, sbase + GOFF_A + ro);
#pragma unroll
                    for (int ni = 0; ni < 4; ni++) {
                        int nj = ni >> 1, o = ni & 1;
                        mma_f16(acc[mi][ni], af, bf[nj][o], bf[nj][o + 2]);
                    }
                }
            }
        }
        if (++st == 3) st = 0;
    }

    const int r  = lane >> 2;
    const int cc = (lane & 3) * 2;
#pragma unroll
    for (int mi = 0; mi < 4; mi++) {
#pragma unroll
        for (int ni = 0; ni < 4; ni++) {
            int m0  = bm + wm * 64 + mi * 16 + r;
            int col = bn + wn * 32 + ni * 8 + cc;
            float b0 = bp[col], b1v = bp[col + 1];
            *(uint32_t*)&g_feats_h[(long)m0 * C_ + col] =
                h2pack(acc[mi][ni][0] + b0, acc[mi][ni][1] + b1v);
            *(uint32_t*)&g_feats_h[(long)(m0 + 8) * C_ + col] =
                h2pack(acc[mi][ni][2] + b0, acc[mi][ni][3] + b1v);
        }
    }
}

// ============================================================
// a|g GEMM: fp16 1-pass, 3-stage; epilogue stores fp16 (+b1 into a)
// grid (8, 98)
// ============================================================
__global__ void __launch_bounds__(256, 2)
ag_mma_kernel(const float* __restrict__ b1)
{
    extern __shared__ __align__(128) char smem[];
    const uint32_t sb = smem_to_u32(smem);
    const int tid = threadIdx.x, lane = tid & 31, w = tid >> 5;
    const int wm = w >> 2, wn = w & 3;
    const int bn = blockIdx.x * 128, bm = blockIdx.y * 128;

    const int lrow = tid >> 1, lseg = tid & 1;
    const long arow = (long)(bm + lrow) * C_ + lseg * 16;
    const long brow = (long)(bn + lrow) * C_ + lseg * 16;

    float acc[4][4][4];
#pragma unroll
    for (int mi = 0; mi < 4; mi++)
#pragma unroll
        for (int ni = 0; ni < 4; ni++)
#pragma unroll
            for (int t = 0; t < 4; t++) acc[mi][ni][t] = 0.f;

    auto cpAB = [&](int c, int st) {
        int k = c * 32;
        const __half* asrc = g_feats_h + arow + k;
        uint32_t ad = sb + st * G_STAGE + GOFF_A + lrow * ROWB + lseg * 32;
        cp16(ad, asrc);
        cp16(ad + 16, asrc + 8);
        const __half* bsrc = g_W1t_h + brow + k;
        uint32_t bd = sb + st * G_STAGE + GOFF_B + lrow * ROWB + lseg * 32;
        cp16(bd, bsrc);
        cp16(bd + 16, bsrc + 8);
    };

    const int NC = C_ / 32;   // 12
    cpAB(0, 0); CP_COMMIT();
    cpAB(1, 1); CP_COMMIT();

    int st = 0;
#pragma unroll 1
    for (int c = 0; c < NC; c++) {
        if (c + 1 < NC) { CP_WAIT1(); } else { CP_WAIT0(); }
        __syncthreads();
        if (c + 2 < NC) {
            int st2 = st + 2; if (st2 >= 3) st2 -= 3;
            cpAB(c + 2, st2);
            CP_COMMIT();
        }
        {
            const uint32_t sbase = sb + st * G_STAGE;
#pragma unroll
            for (int step = 0; step < 2; step++) {
                const uint32_t co = (uint32_t)(step * 32 + (lane >> 4) * 16);
                uint32_t bf[2][4];
#pragma unroll
                for (int nj = 0; nj < 2; nj++) {
                    uint32_t ro = (uint32_t)((wn * 32 + nj * 16 + (lane & 15)) * ROWB) + co;
                    ldm4(bf[nj], sbase + GOFF_B + ro);
                }
#pragma unroll
                for (int mi = 0; mi < 4; mi++) {
                    uint32_t af[4];
                    uint32_t ro = (uint32_t)((wm * 64 + mi * 16 + (lane & 15)) * ROWB) + co;
                    ldm4(af, sbase + GOFF_A + ro);
#pragma unroll
                    for (int ni = 0; ni < 4; ni++) {
                        int nj = ni >> 1, o = ni & 1;
                        mma_f16(acc[mi][ni], af, bf[nj][o], bf[nj][o + 2]);
                    }
                }
            }
        }
        if (++st == 3) st = 0;
    }

    const bool isA = (bn < HM_);
    __half* dst = isA ? g_a : g_g;
    const int nb = isA ? bn : bn - HM_;
    const int r  = lane >> 2;
    const int cc = (lane & 3) * 2;
#pragma unroll
    for (int mi = 0; mi < 4; mi++) {
#pragma unroll
        for (int ni = 0; ni < 4; ni++) {
            int m0  = bm + wm * 64 + mi * 16 + r;
            int col = nb + wn * 32 + ni * 8 + cc;
            float b0 = 0.f, b1v = 0.f;
            if (isA) { b0 = b1[col]; b1v = b1[col + 1]; }
            *(uint32_t*)&dst[(long)m0 * HM_ + col] =
                h2pack(acc[mi][ni][0] + b0, acc[mi][ni][1] + b1v);
            *(uint32_t*)&dst[(long)(m0 + 8) * HM_ + col] =
                h2pack(acc[mi][ni][2] + b0, acc[mi][ni][3] + b1v);
        }
    }
}

// ============================================================
// edge kernel: one block per (b, i); 256 threads, h-pair per thread
// ============================================================
__global__ void __launch_bounds__(256)
edge_b_kernel(float* __restrict__ out)
{
    __shared__ float red[8][28];
    __shared__ float sbias[7];

    const int blk = blockIdx.x;
    const int b   = blk >> 3;
    const int i   = blk & 7;
    const int tid = threadIdx.x, lane = tid & 31, wid = tid >> 5;

    if (tid < 7) sbias[tid] = g_bias7[tid];

    // half2 views: row = s (stride 256 half2), thread owns pair tid
    const __half2* __restrict__ ap =
        (const __half2*)(g_a + ((long)(b * 8 + i) * 49) * HM_) + tid;
    const __half2* __restrict__ gp =
        (const __half2*)(g_g + ((long)(b * 8) * 49) * HM_) + tid;

    float2 acc[8];
#pragma unroll
    for (int j = 0; j < 8; j++) acc[j] = make_float2(0.f, 0.f);

#pragma unroll 7
    for (int s = 0; s < 49; s++) {
        const int so = s * 256;
        float2 av = __half22float2(ap[so]);
#pragma unroll
        for (int j = 0; j < 8; j++) {
            float2 gv = __half22float2(gp[j * (49 * 256) + so]);
            acc[j].x += fmaxf(av.x + gv.x, 0.f);
            acc[j].y += fmaxf(av.y + gv.y, 0.f);
        }
    }

    // W2h rows for h = 2*tid, 2*tid+1: 14 contiguous floats
    float wv[14];
#pragma unroll
    for (int k = 0; k < 14; k++) wv[k] = g_W2h[tid * 14 + k];

    __syncthreads();

#pragma unroll 1
    for (int p0 = 0; p0 < 8; p0 += 4) {
        float pr[28];
#pragma unroll
        for (int q = 0; q < 4; q++)
#pragma unroll
            for (int k = 0; k < 7; k++)
                pr[q * 7 + k] = fmaf(acc[p0 + q].x, wv[k],
                                     acc[p0 + q].y * wv[7 + k]);
#pragma unroll
        for (int t = 0; t < 28; t++) {
#pragma unroll
            for (int off = 16; off; off >>= 1)
                pr[t] += __shfl_down_sync(0xffffffffu, pr[t], off);
        }
        if (lane == 0) {
#pragma unroll
            for (int t = 0; t < 28; t++) red[wid][t] = pr[t];
        }
        __syncthreads();
        if (tid < 28) {
            float v = 0.f;
#pragma unroll
            for (int ww = 0; ww < 8; ww++) v += red[ww][tid];
            int q = tid / 7, k = tid - 7 * q;
            int j = p0 + q;
            int e = b * 64 + i * 8 + j;
            float mf = g_mask[e];
            out[e * 7 + k] = (mf != 0.f) ? (v + sbias[k]) : 0.f;
        }
        __syncthreads();
    }
}

// ============================================================
// fallback zero (only if out_size exceeds the expected constant)
// ============================================================
__global__ void zero_kernel(float* __restrict__ out, int n0, int n1)
{
    int idx = n0 + blockIdx.x * blockDim.x + threadIdx.x;
    if (idx < n1) out[idx] = 0.0f;
}

// ============================================================
extern "C" void kernel_launch(void* const* d_in, const int* in_sizes, int n_in,
                              void* d_out, int out_size)
{
    const float* img    = (const float*)d_in[0];
    const float* pos    = (const float*)d_in[1];
    /* d_in[2] = rot, unused */
    const float* Wpatch = (const float*)d_in[3];
    const float* bpatch = (const float*)d_in[4];
    const float* W1a    = (const float*)d_in[5];
    const float* W1b    = (const float*)d_in[6];
    const float* b1     = (const float*)d_in[7];
    const float* W2     = (const float*)d_in[8];
    const float* b2     = (const float*)d_in[9];
    const float* Wp     = (const float*)d_in[10];
    const float* bp     = (const float*)d_in[11];
    const float* Wpv    = (const float*)d_in[12];
    const float* bpv    = (const float*)d_in[13];
    const float* Wr     = (const float*)d_in[14];
    const float* br     = (const float*)d_in[15];
    const float* Wrv    = (const float*)d_in[16];
    const float* brv    = (const float*)d_in[17];
    float* out = (float*)d_out;

    cudaFuncSetAttribute(patch_mma_kernel,
                         cudaFuncAttributeMaxDynamicSharedMemorySize, G_SMEM);
    cudaFuncSetAttribute(ag_mma_kernel,
                         cudaFuncAttributeMaxDynamicSharedMemorySize, G_SMEM);

    // fused prep: w2h | mask | Wp->fp16 | W1->fp16^T | img->fp16 | node zeros
    prep_all_kernel<<<PB_TOTAL, 256>>>(img, pos, Wpatch, W1a, W1b, W2, b2,
                                       Wp, bp, Wpv, bpv, Wr, br, Wrv, brv, out);
    // patch embedding GEMM
    patch_mma_kernel<<<dim3(C_ / 128, NP / 128), 256, G_SMEM>>>(bpatch);
    // a|g GEMM (+b1 folded into a)
    ag_mma_kernel<<<dim3(NAG / 128, NP / 128), 256, G_SMEM>>>(b1);
    // fused edge MLP + heads
    edge_b_kernel<<<256, 256>>>(out);
    // defensive: zero any output beyond the expected constant size
    int n1 = out_size, n0 = NODE0 + NODEZ;
    if (n1 > n0)
        zero_kernel<<<(n1 - n0 + 255) / 256, 256>>>(out, n0, n1);
}

// round 13
// speedup vs baseline: 1.5739x; 1.0991x over previous
#include <cuda_runtime.h>
#include <cuda_bf16.h>
#include <cuda_fp16.h>
#include <cstdint>

#define B_    32
#define N_    8
#define CIN   3
#define HWD   224
#define PATCH 32
#define S_    49
#define C_    384
#define HM_   512
#define CO_   256
#define NP    12544
#define KCONV 3072
#define NE    2048
#define NAG   1024
#define NODE0 (NE * 7 + NE)        /* 16384 */
#define NODEZ (B_ * N_ * 3600)     /* 921600 */

// ---- scratch (static device globals; no allocation) ----
__device__ __align__(16) __half g_Wph[C_ * KCONV];
__device__ __align__(16) __half g_W1t_h[NAG * C_];
__device__ __align__(16) __half g_feats_h[NP * C_];
__device__ __align__(16) __half g_a[NP * HM_];     // includes +b1
__device__ __align__(16) __half g_g[NP * HM_];
__device__ float g_mask[NE];
__device__ float g_W2h[HM_ * 7];
__device__ float g_bias7[7];

// ---- helpers ----
__device__ __forceinline__ uint32_t smem_to_u32(const void* p) {
    uint32_t a;
    asm("{ .reg .u64 t; cvta.to.shared.u64 t, %1; cvt.u32.u64 %0, t; }" : "=r"(a) : "l"(p));
    return a;
}
__device__ __forceinline__ void cp16(uint32_t dst, const void* src) {
    asm volatile("cp.async.cg.shared.global [%0], [%1], 16;" :: "r"(dst), "l"(src));
}
#define CP_COMMIT() asm volatile("cp.async.commit_group;" ::: "memory")
#define CP_WAIT1()  asm volatile("cp.async.wait_group 1;" ::: "memory")
#define CP_WAIT0()  asm volatile("cp.async.wait_group 0;" ::: "memory")

__device__ __forceinline__ void ldm4(uint32_t* r, uint32_t addr) {
    asm volatile("ldmatrix.sync.aligned.m8n8.x4.shared.b16 {%0,%1,%2,%3}, [%4];"
                 : "=r"(r[0]), "=r"(r[1]), "=r"(r[2]), "=r"(r[3]) : "r"(addr));
}
__device__ __forceinline__ void mma_f16(float* c, const uint32_t* a,
                                        uint32_t b0, uint32_t b1) {
    asm volatile(
        "mma.sync.aligned.m16n8k16.row.col.f32.f16.f16.f32 "
        "{%0,%1,%2,%3}, {%4,%5,%6,%7}, {%8,%9}, {%0,%1,%2,%3};"
        : "+f"(c[0]), "+f"(c[1]), "+f"(c[2]), "+f"(c[3])
        : "r"(a[0]), "r"(a[1]), "r"(a[2]), "r"(a[3]), "r"(b0), "r"(b1));
}
__device__ __forceinline__ uint32_t h2pack(float x, float y) {
    __half2 h = __floats2half2_rn(x, y);
    return *reinterpret_cast<uint32_t*>(&h);
}

// smem rows: 32 fp16 (64B) padded to 80B (conflict-free mod 128)
#define ROWB    80
#define TILE_B  (128 * ROWB)
#define G_STAGE  (2 * TILE_B)
#define G_SMEM   (3 * G_STAGE)
#define GOFF_A   0
#define GOFF_B   TILE_B

// ============================================================
// Fused prep: w2h | mask | wp | w1-transpose | node-zeros
// ============================================================
#define PB_W2H  64
#define PB_MASK 8
#define PB_WP   ((C_ * KCONV / 4) / 256)     /* 1152 */
#define PB_W1T  ((NAG / 64) * (C_ / 64))     /* 96 */
#define PB_ZERO (NODEZ / (256 * 16))         /* 225 */
#define PB_TOTAL (PB_W2H + PB_MASK + PB_WP + PB_W1T + PB_ZERO)

__device__ __forceinline__ float head_w(int o, int k,
                                        const float* Wph, const float* Wpv,
                                        const float* Wr, const float* Wrv)
{
    if (k < 2) return Wph[o * 2 + k];
    if (k < 4) return Wpv[o * 2 + (k - 2)];
    if (k < 6) return Wr[o * 2 + (k - 4)];
    return Wrv[o];
}

__global__ void __launch_bounds__(256)
prep_all_kernel(const float* __restrict__ pos,
                const float* __restrict__ Wp,
                const float* __restrict__ W1a, const float* __restrict__ W1b,
                const float* __restrict__ W2,  const float* __restrict__ b2,
                const float* __restrict__ Wph, const float* __restrict__ bph,
                const float* __restrict__ Wpv, const float* __restrict__ bpv,
                const float* __restrict__ Wr,  const float* __restrict__ br,
                const float* __restrict__ Wrv, const float* __restrict__ brv,
                float* __restrict__ out)
{
    __shared__ float ts[64][65];   // also covers sW usage (first 256*7 floats)
    float (*sW)[7] = (float (*)[7])&ts[0][0];
    int bid = blockIdx.x;
    const int tid = threadIdx.x;

    if (bid < PB_W2H) {
        const int lane = tid & 31, wid = tid >> 5;
        if (tid < CO_) {
#pragma unroll
            for (int k = 0; k < 7; k++)
                sW[tid][k] = head_w(tid, k, Wph, Wpv, Wr, Wrv);
        }
        __syncthreads();
        const int h = bid * 8 + wid;
        float acc[7] = {0, 0, 0, 0, 0, 0, 0};
#pragma unroll
        for (int t = 0; t < 8; t++) {
            int o = lane + 32 * t;
            float w2 = W2[h * CO_ + o];
#pragma unroll
            for (int k = 0; k < 7; k++)
                acc[k] = fmaf(w2, sW[o][k], acc[k]);
        }
#pragma unroll
        for (int k = 0; k < 7; k++) {
#pragma unroll
            for (int off = 16; off; off >>= 1)
                acc[k] += __shfl_down_sync(0xffffffffu, acc[k], off);
        }
        if (lane == 0) {
#pragma unroll
            for (int k = 0; k < 7; k++)
                g_W2h[h * 7 + k] = acc[k] * (1.0f / 49.0f);
        }
        if (bid == 0 && tid < 7) {
            float sum = 0.f;
            for (int o = 0; o < CO_; o++)
                sum = fmaf(b2[o], sW[o][tid], sum);
            float bb = (tid < 2) ? bph[tid] : (tid < 4) ? bpv[tid - 2]
                     : (tid < 6) ? br[tid - 4] : brv[0];
            g_bias7[tid] = sum + bb;
        }
        return;
    }
    bid -= PB_W2H;

    if (bid < PB_MASK) {
        int e = bid * 256 + tid;
        int b = e >> 6, i = (e >> 3) & 7, j = e & 7;
        float xi = pos[(b * N_ + i) * 3 + 0], yi = pos[(b * N_ + i) * 3 + 1];
        float xj = pos[(b * N_ + j) * 3 + 0], yj = pos[(b * N_ + j) * 3 + 1];
        float dx = xi - xj, dy = yi - yj;
        float d2 = __fadd_rn(__fmul_rn(dx, dx), __fmul_rn(dy, dy));
        float m = (d2 < 0.25f && i != j) ? 1.0f : 0.0f;
        g_mask[e] = m;
        out[NE * 7 + e] = m;
        return;
    }
    bid -= PB_MASK;

    if (bid < PB_WP) {
        int i4 = bid * 256 + tid;
        float4 v = *(const float4*)&Wp[(long)i4 * 4];
        *(uint2*)&g_Wph[(long)i4 * 4] = make_uint2(h2pack(v.x, v.y), h2pack(v.z, v.w));
        return;
    }
    bid -= PB_WP;

    if (bid < PB_W1T) {
        // tiled transpose: 64n x 64k tile; reads coalesced in n, writes in k
        int nt = bid / (C_ / 64);          // 0..15
        int kt = bid - nt * (C_ / 64);     // 0..5
        int n0 = nt * 64, k0 = kt * 64;
#pragma unroll
        for (int it = 0; it < 16; it++) {
            int idx = it * 256 + tid;
            int kk = idx >> 6, nn = idx & 63;
            int n = n0 + nn;
            float v = (n < HM_) ? W1a[(k0 + kk) * HM_ + n]
                                : W1b[(k0 + kk) * HM_ + (n - HM_)];
            ts[kk][nn] = v;
        }
        __syncthreads();
#pragma unroll
        for (int it = 0; it < 16; it++) {
            int idx = it * 256 + tid;
            int nn = idx >> 6, kk = idx & 63;
            g_W1t_h[(n0 + nn) * C_ + k0 + kk] = __float2half_rn(ts[kk][nn]);
        }
        return;
    }
    bid -= PB_W1T;

    {   // node_preds zeros
        int base = NODE0 + (bid * 256 + tid) * 16;
        float4 z = make_float4(0.f, 0.f, 0.f, 0.f);
        *(float4*)&out[base]      = z;
        *(float4*)&out[base + 4]  = z;
        *(float4*)&out[base + 8]  = z;
        *(float4*)&out[base + 12] = z;
    }
}

// ============================================================
// Patch GEMM: feats = im2row(img fp32, converted inline) x Wp^T
// A: LDG fp32 -> cvt -> STS, reg-double-buffered; B: 3-stage cp.async.
// grid (3, 98), one __syncthreads per chunk.
// ============================================================
__global__ void __launch_bounds__(256, 2)
patch_mma_kernel(const float* __restrict__ img, const float* __restrict__ bp)
{
    extern __shared__ __align__(128) char smem[];
    const uint32_t sb = smem_to_u32(smem);
    const int tid = threadIdx.x, lane = tid & 31, w = tid >> 5;
    const int wm = w >> 2, wn = w & 3;
    const int bn = blockIdx.x * 128, bm = blockIdx.y * 128;

    // A loader: row = tid>>1, seg = tid&1 -> 16 consecutive fp32
    const int lrow = tid >> 1, lseg = tid & 1;
    int abase;
    {
        int p  = bm + lrow;
        int n  = p / 49;
        int s  = p - n * 49;
        int py = s / 7, px = s - py * 7;
        abase = (n * CIN * HWD + py * PATCH) * HWD + px * PATCH + lseg * 16;
    }
    const long brow = (long)(bn + lrow) * KCONV + lseg * 16;

    float acc[4][4][4];
#pragma unroll
    for (int mi = 0; mi < 4; mi++)
#pragma unroll
        for (int ni = 0; ni < 4; ni++)
#pragma unroll
            for (int t = 0; t < 4; t++) acc[mi][ni][t] = 0.f;

    float4 areg[4];

    auto ldA = [&](int c) {
        int k  = c * 32;
        int ci = k >> 10, rem = k & 1023, y = rem >> 5;
        const float4* src = (const float4*)(img + abase + ci * (HWD * HWD) + y * HWD);
        areg[0] = src[0]; areg[1] = src[1]; areg[2] = src[2]; areg[3] = src[3];
    };
    auto stA = [&](int st) {
        uint32_t ad = sb + st * G_STAGE + GOFF_A + lrow * ROWB + lseg * 32;
        uint4 v0 = make_uint4(h2pack(areg[0].x, areg[0].y), h2pack(areg[0].z, areg[0].w),
                              h2pack(areg[1].x, areg[1].y), h2pack(areg[1].z, areg[1].w));
        uint4 v1 = make_uint4(h2pack(areg[2].x, areg[2].y), h2pack(areg[2].z, areg[2].w),
                              h2pack(areg[3].x, areg[3].y), h2pack(areg[3].z, areg[3].w));
        asm volatile("st.shared.v4.b32 [%0], {%1,%2,%3,%4};"
                     :: "r"(ad), "r"(v0.x), "r"(v0.y), "r"(v0.z), "r"(v0.w));
        asm volatile("st.shared.v4.b32 [%0], {%1,%2,%3,%4};"
                     :: "r"(ad + 16), "r"(v1.x), "r"(v1.y), "r"(v1.z), "r"(v1.w));
    };
    auto cpB = [&](int c, int st) {
        int k = c * 32;
        const __half* bsrc = g_Wph + brow + k;
        uint32_t bd = sb + st * G_STAGE + GOFF_B + lrow * ROWB + lseg * 32;
        cp16(bd, bsrc);
        cp16(bd + 16, bsrc + 8);
    };

    const int NC = KCONV / 32;   // 96
    ldA(0);
    cpB(0, 0); CP_COMMIT();
    cpB(1, 1); CP_COMMIT();

    int st = 0;
#pragma unroll 1
    for (int c = 0; c < NC; c++) {
        stA(st);
        if (c + 1 < NC) { CP_WAIT1(); } else { CP_WAIT0(); }
        __syncthreads();
        if (c + 2 < NC) {
            int st2 = st + 2; if (st2 >= 3) st2 -= 3;
            cpB(c + 2, st2);
            CP_COMMIT();
        }
        if (c + 1 < NC) ldA(c + 1);
        {
            const uint32_t sbase = sb + st * G_STAGE;
#pragma unroll
            for (int step = 0; step < 2; step++) {
                const uint32_t co = (uint32_t)(step * 32 + (lane >> 4) * 16);
                uint32_t bf[2][4];
#pragma unroll
                for (int nj = 0; nj < 2; nj++) {
                    uint32_t ro = (uint32_t)((wn * 32 + nj * 16 + (lane & 15)) * ROWB) + co;
                    ldm4(bf[nj], sbase + GOFF_B + ro);
                }
#pragma unroll
                for (int mi = 0; mi < 4; mi++) {
                    uint32_t af[4];
                    uint32_t ro = (uint32_t)((wm * 64 + mi * 16 + (lane & 15)) * ROWB) + co;
                    ldm4(af, sbase + GOFF_A + ro);
#pragma unroll
                    for (int ni = 0; ni < 4; ni++) {
                        int nj = ni >> 1, o = ni & 1;
                        mma_f16(acc[mi][ni], af, bf[nj][o], bf[nj][o + 2]);
                    }
                }
            }
        }
        if (++st == 3) st = 0;
    }

    const int r  = lane >> 2;
    const int cc = (lane & 3) * 2;
#pragma unroll
    for (int mi = 0; mi < 4; mi++) {
#pragma unroll
        for (int ni = 0; ni < 4; ni++) {
            int m0  = bm + wm * 64 + mi * 16 + r;
            int col = bn + wn * 32 + ni * 8 + cc;
            float b0 = bp[col], b1v = bp[col + 1];
            *(uint32_t*)&g_feats_h[(long)m0 * C_ + col] =
                h2pack(acc[mi][ni][0] + b0, acc[mi][ni][1] + b1v);
            *(uint32_t*)&g_feats_h[(long)(m0 + 8) * C_ + col] =
                h2pack(acc[mi][ni][2] + b0, acc[mi][ni][3] + b1v);
        }
    }
}

// ============================================================
// a|g GEMM: fp16 1-pass, 3-stage; epilogue stores fp16 (+b1 into a)
// grid (8, 98)
// ============================================================
__global__ void __launch_bounds__(256, 2)
ag_mma_kernel(const float* __restrict__ b1)
{
    extern __shared__ __align__(128) char smem[];
    const uint32_t sb = smem_to_u32(smem);
    const int tid = threadIdx.x, lane = tid & 31, w = tid >> 5;
    const int wm = w >> 2, wn = w & 3;
    const int bn = blockIdx.x * 128, bm = blockIdx.y * 128;

    const int lrow = tid >> 1, lseg = tid & 1;
    const long arow = (long)(bm + lrow) * C_ + lseg * 16;
    const long brow = (long)(bn + lrow) * C_ + lseg * 16;

    float acc[4][4][4];
#pragma unroll
    for (int mi = 0; mi < 4; mi++)
#pragma unroll
        for (int ni = 0; ni < 4; ni++)
#pragma unroll
            for (int t = 0; t < 4; t++) acc[mi][ni][t] = 0.f;

    auto cpAB = [&](int c, int st) {
        int k = c * 32;
        const __half* asrc = g_feats_h + arow + k;
        uint32_t ad = sb + st * G_STAGE + GOFF_A + lrow * ROWB + lseg * 32;
        cp16(ad, asrc);
        cp16(ad + 16, asrc + 8);
        const __half* bsrc = g_W1t_h + brow + k;
        uint32_t bd = sb + st * G_STAGE + GOFF_B + lrow * ROWB + lseg * 32;
        cp16(bd, bsrc);
        cp16(bd + 16, bsrc + 8);
    };

    const int NC = C_ / 32;   // 12
    cpAB(0, 0); CP_COMMIT();
    cpAB(1, 1); CP_COMMIT();

    int st = 0;
#pragma unroll 1
    for (int c = 0; c < NC; c++) {
        if (c + 1 < NC) { CP_WAIT1(); } else { CP_WAIT0(); }
        __syncthreads();
        if (c + 2 < NC) {
            int st2 = st + 2; if (st2 >= 3) st2 -= 3;
            cpAB(c + 2, st2);
            CP_COMMIT();
        }
        {
            const uint32_t sbase = sb + st * G_STAGE;
#pragma unroll
            for (int step = 0; step < 2; step++) {
                const uint32_t co = (uint32_t)(step * 32 + (lane >> 4) * 16);
                uint32_t bf[2][4];
#pragma unroll
                for (int nj = 0; nj < 2; nj++) {
                    uint32_t ro = (uint32_t)((wn * 32 + nj * 16 + (lane & 15)) * ROWB) + co;
                    ldm4(bf[nj], sbase + GOFF_B + ro);
                }
#pragma unroll
                for (int mi = 0; mi < 4; mi++) {
                    uint32_t af[4];
                    uint32_t ro = (uint32_t)((wm * 64 + mi * 16 + (lane & 15)) * ROWB) + co;
                    ldm4(af, sbase + GOFF_A + ro);
#pragma unroll
                    for (int ni = 0; ni < 4; ni++) {
                        int nj = ni >> 1, o = ni & 1;
                        mma_f16(acc[mi][ni], af, bf[nj][o], bf[nj][o + 2]);
                    }
                }
            }
        }
        if (++st == 3) st = 0;
    }

    const bool isA = (bn < HM_);
    __half* dst = isA ? g_a : g_g;
    const int nb = isA ? bn : bn - HM_;
    const int r  = lane >> 2;
    const int cc = (lane & 3) * 2;
#pragma unroll
    for (int mi = 0; mi < 4; mi++) {
#pragma unroll
        for (int ni = 0; ni < 4; ni++) {
            int m0  = bm + wm * 64 + mi * 16 + r;
            int col = nb + wn * 32 + ni * 8 + cc;
            float b0 = 0.f, b1v = 0.f;
            if (isA) { b0 = b1[col]; b1v = b1[col + 1]; }
            *(uint32_t*)&dst[(long)m0 * HM_ + col] =
                h2pack(acc[mi][ni][0] + b0, acc[mi][ni][1] + b1v);
            *(uint32_t*)&dst[(long)(m0 + 8) * HM_ + col] =
                h2pack(acc[mi][ni][2] + b0, acc[mi][ni][3] + b1v);
        }
    }
}

// ============================================================
// edge kernel: block per (b, i, j-half); 256 threads, h-pair per thread
// ============================================================
__global__ void __launch_bounds__(256)
edge_b_kernel(float* __restrict__ out)
{
    __shared__ float red[8][28];
    __shared__ float sbias[7];

    const int blk = blockIdx.x;
    const int b   = blk >> 4;
    const int i   = (blk >> 1) & 7;
    const int jh  = blk & 1;
    const int tid = threadIdx.x, lane = tid & 31, wid = tid >> 5;

    if (tid < 7) sbias[tid] = g_bias7[tid];

    const __half2* __restrict__ ap =
        (const __half2*)(g_a + ((long)(b * 8 + i) * 49) * HM_) + tid;
    const __half2* __restrict__ gp =
        (const __half2*)(g_g + ((long)(b * 8 + jh * 4) * 49) * HM_) + tid;

    float2 acc[4];
#pragma unroll
    for (int j = 0; j < 4; j++) acc[j] = make_float2(0.f, 0.f);

#pragma unroll 7
    for (int s = 0; s < 49; s++) {
        const int so = s * 256;
        float2 av = __half22float2(ap[so]);
#pragma unroll
        for (int j = 0; j < 4; j++) {
            float2 gv = __half22float2(gp[j * (49 * 256) + so]);
            acc[j].x += fmaxf(av.x + gv.x, 0.f);
            acc[j].y += fmaxf(av.y + gv.y, 0.f);
        }
    }

    float wv[14];
#pragma unroll
    for (int k = 0; k < 14; k++) wv[k] = g_W2h[tid * 14 + k];

    __syncthreads();

    float pr[28];
#pragma unroll
    for (int q = 0; q < 4; q++)
#pragma unroll
        for (int k = 0; k < 7; k++)
            pr[q * 7 + k] = fmaf(acc[q].x, wv[k], acc[q].y * wv[7 + k]);
#pragma unroll
    for (int t = 0; t < 28; t++) {
#pragma unroll
        for (int off = 16; off; off >>= 1)
            pr[t] += __shfl_down_sync(0xffffffffu, pr[t], off);
    }
    if (lane == 0) {
#pragma unroll
        for (int t = 0; t < 28; t++) red[wid][t] = pr[t];
    }
    __syncthreads();
    if (tid < 28) {
        float v = 0.f;
#pragma unroll
        for (int ww = 0; ww < 8; ww++) v += red[ww][tid];
        int q = tid / 7, k = tid - 7 * q;
        int j = jh * 4 + q;
        int e = b * 64 + i * 8 + j;
        float mf = g_mask[e];
        out[e * 7 + k] = (mf != 0.f) ? (v + sbias[k]) : 0.f;
    }
}

// ============================================================
// fallback zero
// ============================================================
__global__ void zero_kernel(float* __restrict__ out, int n0, int n1)
{
    int idx = n0 + blockIdx.x * blockDim.x + threadIdx.x;
    if (idx < n1) out[idx] = 0.0f;
}

// ============================================================
extern "C" void kernel_launch(void* const* d_in, const int* in_sizes, int n_in,
                              void* d_out, int out_size)
{
    const float* img    = (const float*)d_in[0];
    const float* pos    = (const float*)d_in[1];
    /* d_in[2] = rot, unused */
    const float* Wpatch = (const float*)d_in[3];
    const float* bpatch = (const float*)d_in[4];
    const float* W1a    = (const float*)d_in[5];
    const float* W1b    = (const float*)d_in[6];
    const float* b1     = (const float*)d_in[7];
    const float* W2     = (const float*)d_in[8];
    const float* b2     = (const float*)d_in[9];
    const float* Wp     = (const float*)d_in[10];
    const float* bp     = (const float*)d_in[11];
    const float* Wpv    = (const float*)d_in[12];
    const float* bpv    = (const float*)d_in[13];
    const float* Wr     = (const float*)d_in[14];
    const float* br     = (const float*)d_in[15];
    const float* Wrv    = (const float*)d_in[16];
    const float* brv    = (const float*)d_in[17];
    float* out = (float*)d_out;

    cudaFuncSetAttribute(patch_mma_kernel,
                         cudaFuncAttributeMaxDynamicSharedMemorySize, G_SMEM);
    cudaFuncSetAttribute(ag_mma_kernel,
                         cudaFuncAttributeMaxDynamicSharedMemorySize, G_SMEM);

    // fused prep: w2h | mask | Wp->fp16 | W1 transpose->fp16 | node zeros
    prep_all_kernel<<<PB_TOTAL, 256>>>(pos, Wpatch, W1a, W1b, W2, b2,
                                       Wp, bp, Wpv, bpv, Wr, br, Wrv, brv, out);
    // patch embedding GEMM (fp32 img read + inline convert)
    patch_mma_kernel<<<dim3(C_ / 128, NP / 128), 256, G_SMEM>>>(img, bpatch);
    // a|g GEMM (+b1 folded into a)
    ag_mma_kernel<<<dim3(NAG / 128, NP / 128), 256, G_SMEM>>>(b1);
    // fused edge MLP + heads
    edge_b_kernel<<<512, 256>>>(out);
    // defensive: zero any output beyond the expected constant size
    int n1 = out_size, n0 = NODE0 + NODEZ;
    if (n1 > n0)
        zero_kernel<<<(n1 - n0 + 255) / 256, 256>>>(out, n0, n1);
}